// round 4
// baseline (speedup 1.0000x reference)
#include <cuda_runtime.h>
#include <cstdint>

#define HW   16384
#define CDIM 192
#define C3   576
#define BATCH 8
#define HEADS 8
#define CHD  24

// ---------------- scratch (device globals: allocation-free rule) ----------------
__device__ float g_qkv [75497472];   // [8,576,16384] after 1x1 conv
__device__ float g_v   [25165824];   // [8,192,16384] depthwise-conv'd v
__device__ float g_var [BATCH*CDIM];
__device__ float g_norm[BATCH*384];  // accumulated sumsq for q (0..191) and k (192..383)
__device__ float g_S   [BATCH*HEADS*CHD*CHD];
__device__ float g_M   [BATCH*CDIM*CDIM];

__device__ __forceinline__ uint32_t smem_u32(const void* p) {
    uint32_t a;
    asm("{ .reg .u64 t; cvta.to.shared.u64 t, %1; cvt.u32.u64 %0, t; }" : "=r"(a) : "l"(p));
    return a;
}
__device__ __forceinline__ uint32_t f2tf32(float f) {
    uint32_t o;
    asm("cvt.rna.tf32.f32 %0, %1;" : "=r"(o) : "f"(f));
    return o;
}
__device__ __forceinline__ void mma_tf32(float* c, const uint32_t* a, const uint32_t* b) {
    asm volatile(
        "mma.sync.aligned.m16n8k8.row.col.f32.tf32.tf32.f32 "
        "{%0,%1,%2,%3}, {%4,%5,%6,%7}, {%8,%9}, {%0,%1,%2,%3};"
        : "+f"(c[0]), "+f"(c[1]), "+f"(c[2]), "+f"(c[3])
        : "r"(a[0]), "r"(a[1]), "r"(a[2]), "r"(a[3]), "r"(b[0]), "r"(b[1]));
}
__device__ __forceinline__ void cp_async16(uint32_t dst, const void* src) {
    asm volatile("cp.async.cg.shared.global [%0], [%1], 16;" :: "r"(dst), "l"(src) : "memory");
}

// ================= tf32 mma.sync batched GEMM: C[M,N] = A[M,K] @ B[K,N] =================
__global__ void __launch_bounds__(256, 2) gemm_mma(
    const float* __restrict__ A, const float* __restrict__ B, float* __restrict__ C,
    int M, int N, int K, long long sA, long long sB, long long sC)
{
    __shared__ float As[2][16][72];
    __shared__ float Bs[2][16][264];
    const int tid  = threadIdx.x;
    const int lane = tid & 31;
    const int wid  = tid >> 5;
    const int g    = lane >> 2;
    const int t    = lane & 3;
    const float* Ab = A + (long long)blockIdx.z * sA;
    const float* Bb = B + (long long)blockIdx.z * sB;
    float*       Cb = C + (long long)blockIdx.z * sC;
    const int bm = blockIdx.y * 64;
    const int bn = blockIdx.x * 256;

    const int am    = tid & 63;
    const int ak    = (tid >> 6) << 2;
    const int bnoff = (tid & 63) << 2;
    const int bk    = tid >> 6;

    float acc[4][4][4];
    #pragma unroll
    for (int i = 0; i < 4; i++)
        #pragma unroll
        for (int j = 0; j < 4; j++)
            #pragma unroll
            for (int l = 0; l < 4; l++) acc[i][j][l] = 0.f;

    float4 areg = *(const float4*)&Ab[(size_t)(bm + am) * K + ak];
    #pragma unroll
    for (int p = 0; p < 4; p++)
        cp_async16(smem_u32(&Bs[0][bk + p * 4][bnoff]),
                   &Bb[(size_t)(bk + p * 4) * N + bn + bnoff]);
    asm volatile("cp.async.commit_group;" ::: "memory");
    As[0][ak + 0][am] = __uint_as_float(f2tf32(areg.x));
    As[0][ak + 1][am] = __uint_as_float(f2tf32(areg.y));
    As[0][ak + 2][am] = __uint_as_float(f2tf32(areg.z));
    As[0][ak + 3][am] = __uint_as_float(f2tf32(areg.w));
    asm volatile("cp.async.wait_group 0;" ::: "memory");
    __syncthreads();

    const int nk = K >> 4;
    for (int i = 0; i < nk; i++) {
        const int s = i & 1;
        float4 anext;
        if (i + 1 < nk) {
            const int k0 = (i + 1) << 4;
            anext = *(const float4*)&Ab[(size_t)(bm + am) * K + k0 + ak];
            #pragma unroll
            for (int p = 0; p < 4; p++)
                cp_async16(smem_u32(&Bs[s ^ 1][bk + p * 4][bnoff]),
                           &Bb[(size_t)(k0 + bk + p * 4) * N + bn + bnoff]);
            asm volatile("cp.async.commit_group;" ::: "memory");
        }
        #pragma unroll
        for (int kk = 0; kk < 2; kk++) {
            uint32_t af[4][4];
            #pragma unroll
            for (int ma = 0; ma < 4; ma++) {
                af[ma][0] = __float_as_uint(As[s][kk * 8 + t    ][ma * 16 + g    ]);
                af[ma][1] = __float_as_uint(As[s][kk * 8 + t    ][ma * 16 + g + 8]);
                af[ma][2] = __float_as_uint(As[s][kk * 8 + t + 4][ma * 16 + g    ]);
                af[ma][3] = __float_as_uint(As[s][kk * 8 + t + 4][ma * 16 + g + 8]);
            }
            uint32_t bf[4][2];
            #pragma unroll
            for (int na = 0; na < 4; na++) {
                bf[na][0] = f2tf32(Bs[s][kk * 8 + t    ][wid * 32 + na * 8 + g]);
                bf[na][1] = f2tf32(Bs[s][kk * 8 + t + 4][wid * 32 + na * 8 + g]);
            }
            #pragma unroll
            for (int ma = 0; ma < 4; ma++)
                #pragma unroll
                for (int na = 0; na < 4; na++)
                    mma_tf32(acc[ma][na], af[ma], bf[na]);
        }
        if (i + 1 < nk) {
            As[s ^ 1][ak + 0][am] = __uint_as_float(f2tf32(anext.x));
            As[s ^ 1][ak + 1][am] = __uint_as_float(f2tf32(anext.y));
            As[s ^ 1][ak + 2][am] = __uint_as_float(f2tf32(anext.z));
            As[s ^ 1][ak + 3][am] = __uint_as_float(f2tf32(anext.w));
            asm volatile("cp.async.wait_group 0;" ::: "memory");
        }
        __syncthreads();
    }
    #pragma unroll
    for (int ma = 0; ma < 4; ma++) {
        #pragma unroll
        for (int na = 0; na < 4; na++) {
            const int row = bm + ma * 16 + g;
            const int col = bn + wid * 32 + na * 8 + (t << 1);
            *(float2*)&Cb[(size_t)row * N + col]       = make_float2(acc[ma][na][0], acc[ma][na][1]);
            *(float2*)&Cb[(size_t)(row + 8) * N + col] = make_float2(acc[ma][na][2], acc[ma][na][3]);
        }
    }
}

// ---------------- zero S + norm accumulators ----------------
__global__ void k_zero() {
    int i = blockIdx.x * blockDim.x + threadIdx.x;
    if (i < BATCH*HEADS*CHD*CHD) g_S[i] = 0.f;
    else if (i < BATCH*HEADS*CHD*CHD + BATCH*384) g_norm[i - BATCH*HEADS*CHD*CHD] = 0.f;
}

// ---------------- depthwise 3x3 on x + unbiased variance, 4px/thread ----------------
__global__ __launch_bounds__(256) void k_dw_var(const float* __restrict__ x,
                                                const float* __restrict__ wdw)
{
    __shared__ float s[66*132];
    __shared__ float red[64];
    const int bc = blockIdx.x;
    const float* plane = x + (size_t)bc * HW;
    const int c = bc % CDIM;
    const int tid = threadIdx.x;
    float w9[9];
    #pragma unroll
    for (int i = 0; i < 9; i++) w9[i] = wdw[c*9 + i];
    float sum = 0.f, sq = 0.f;
    for (int half = 0; half < 2; half++) {
        if (half) __syncthreads();
        const int y0 = half * 64;
        for (int i = tid; i < 66*132; i += 256) {
            int r = i / 132, cc = i % 132;
            int y = y0 + r - 1, xx = cc - 1;
            s[i] = (cc < 130 && y >= 0 && y < 128 && (unsigned)xx < 128u) ? plane[y*128 + xx] : 0.f;
        }
        __syncthreads();
        for (int p = tid; p < 2048; p += 256) {
            int yl = p >> 5, x4 = (p & 31) << 2;
            const float* bp = &s[yl*132 + x4];
            float4 a0 = *(const float4*)bp,        a1 = *(const float4*)(bp + 4);
            float4 b0 = *(const float4*)(bp+132),  b1 = *(const float4*)(bp + 136);
            float4 c0 = *(const float4*)(bp+264),  c1 = *(const float4*)(bp + 268);
            float r0[6] = {a0.x,a0.y,a0.z,a0.w,a1.x,a1.y};
            float r1[6] = {b0.x,b0.y,b0.z,b0.w,b1.x,b1.y};
            float r2[6] = {c0.x,c0.y,c0.z,c0.w,c1.x,c1.y};
            #pragma unroll
            for (int i = 0; i < 4; i++) {
                float v = r0[i]*w9[0] + r0[i+1]*w9[1] + r0[i+2]*w9[2]
                        + r1[i]*w9[3] + r1[i+1]*w9[4] + r1[i+2]*w9[5]
                        + r2[i]*w9[6] + r2[i+1]*w9[7] + r2[i+2]*w9[8];
                sum += v; sq += v*v;
            }
        }
    }
    #pragma unroll
    for (int o = 16; o > 0; o >>= 1) {
        sum += __shfl_down_sync(0xffffffffu, sum, o);
        sq  += __shfl_down_sync(0xffffffffu, sq,  o);
    }
    if ((tid & 31) == 0) { red[tid>>5] = sum; red[32 + (tid>>5)] = sq; }
    __syncthreads();
    if (tid == 0) {
        float S = 0.f, Q = 0.f;
        #pragma unroll
        for (int i = 0; i < 8; i++) { S += red[i]; Q += red[32+i]; }
        g_var[bc] = (Q - S*S*(1.f/16384.f)) * (1.f/16383.f);
    }
}

// ---------------- depthwise 3x3 on v channels only, 4px/thread ----------------
__global__ __launch_bounds__(256) void k_dwv(const float* __restrict__ wdw)
{
    __shared__ float s[66*132];
    const int bc = blockIdx.x;                 // b*192 + c (v channel)
    const int b = bc / CDIM, c = bc % CDIM;
    const float* plane = g_qkv + ((size_t)b*C3 + 384 + c) * HW;
    float*       outp  = g_v   + (size_t)bc * HW;
    const int tid = threadIdx.x;
    float w9[9];
    #pragma unroll
    for (int i = 0; i < 9; i++) w9[i] = wdw[(384 + c)*9 + i];
    for (int half = 0; half < 2; half++) {
        if (half) __syncthreads();
        const int y0 = half * 64;
        for (int i = tid; i < 66*132; i += 256) {
            int r = i / 132, cc = i % 132;
            int y = y0 + r - 1, xx = cc - 1;
            s[i] = (cc < 130 && y >= 0 && y < 128 && (unsigned)xx < 128u) ? plane[y*128 + xx] : 0.f;
        }
        __syncthreads();
        for (int p = tid; p < 2048; p += 256) {
            int yl = p >> 5, x4 = (p & 31) << 2;
            const float* bp = &s[yl*132 + x4];
            float4 a0 = *(const float4*)bp,        a1 = *(const float4*)(bp + 4);
            float4 b0 = *(const float4*)(bp+132),  b1 = *(const float4*)(bp + 136);
            float4 c0 = *(const float4*)(bp+264),  c1 = *(const float4*)(bp + 268);
            float r0[6] = {a0.x,a0.y,a0.z,a0.w,a1.x,a1.y};
            float r1[6] = {b0.x,b0.y,b0.z,b0.w,b1.x,b1.y};
            float r2[6] = {c0.x,c0.y,c0.z,c0.w,c1.x,c1.y};
            float4 o;
            float* ov = (float*)&o;
            #pragma unroll
            for (int i = 0; i < 4; i++)
                ov[i] = r0[i]*w9[0] + r0[i+1]*w9[1] + r0[i+2]*w9[2]
                      + r1[i]*w9[3] + r1[i+1]*w9[4] + r1[i+2]*w9[5]
                      + r2[i]*w9[6] + r2[i+1]*w9[7] + r2[i+2]*w9[8];
            *(float4*)&outp[(y0 + yl)*128 + x4] = o;
        }
    }
}

// ---------------- FUSED: q/k depthwise conv + S = q@k^T + l2 norms ----------------
// grid (64 bh, 32 row-chunks of 4 image rows = 512 px), 256 threads.
// Dyn SMEM floats: qs[24*512] | ks[24*512] | halo[784] | ws[432] | snorm[48]
__global__ __launch_bounds__(256) void k_qks(const float* __restrict__ wdw)
{
    extern __shared__ float dsm[];
    float* qs    = dsm;
    float* ks    = dsm + 12288;
    float* halo  = dsm + 24576;
    float* ws    = dsm + 25360;
    float* snorm = dsm + 25792;

    const int bh = blockIdx.x;
    const int b = bh >> 3, h = bh & 7;
    const int r0 = blockIdx.y * 4;
    const int tid = threadIdx.x;

    if (tid < 48) snorm[tid] = 0.f;
    for (int i = tid; i < 432; i += 256) {
        int ch = i / 9, r = i % 9;
        int gch = (ch < 24) ? (h*24 + ch) : (192 + h*24 + (ch - 24));
        ws[i] = wdw[gch*9 + r];
    }

    const int j0 = tid * 2;
    const int row = j0 >> 7, col = j0 & 127;

    for (int ch = 0; ch < 48; ch++) {
        const int gch = (ch < 24) ? (h*24 + ch) : (192 + h*24 + (ch - 24));
        const float* plane = g_qkv + ((size_t)b*C3 + gch) * HW;
        __syncthreads();   // protect halo (prev readers done) & first-iter init ordering
        for (int i = tid; i < 780; i += 256) {
            int r = i / 130, cc = i % 130;
            int y = r0 + r - 1, xx = cc - 1;
            halo[i] = (y >= 0 && y < 128 && (unsigned)xx < 128u) ? plane[y*128 + xx] : 0.f;
        }
        __syncthreads();
        const float* wp = &ws[ch*9];
        float w0=wp[0],w1=wp[1],w2=wp[2],w3=wp[3],w4=wp[4],w5=wp[5],w6=wp[6],w7=wp[7],w8=wp[8];
        const float* bp = &halo[row*130 + col];
        float v0 = bp[0]*w0 + bp[1]*w1 + bp[2]*w2
                 + bp[130]*w3 + bp[131]*w4 + bp[132]*w5
                 + bp[260]*w6 + bp[261]*w7 + bp[262]*w8;
        float v1 = bp[1]*w0 + bp[2]*w1 + bp[3]*w2
                 + bp[131]*w3 + bp[132]*w4 + bp[133]*w5
                 + bp[261]*w6 + bp[262]*w7 + bp[263]*w8;
        float* dst = (ch < 24) ? (qs + ch*512) : (ks + (ch - 24)*512);
        *(float2*)&dst[j0] = make_float2(v0, v1);
        float sq = v0*v0 + v1*v1;
        #pragma unroll
        for (int o = 16; o > 0; o >>= 1) sq += __shfl_down_sync(0xffffffffu, sq, o);
        if ((tid & 31) == 0) atomicAdd(&snorm[ch], sq);
    }
    __syncthreads();

    // ---- S accumulation: 36 groups (4x4 tile of 24x24) x 4 subs = 144 threads ----
    if (tid < 144) {
        const int sub = tid & 3;
        const int cd  = tid >> 2;
        const int c0 = (cd / 6) * 4, d0 = (cd % 6) * 4;
        float acc[4][4] = {};
        int jj = tid & 511;        // = 4*cd+sub : per-lane distinct mod 32 -> conflict-free
        for (int t = 0; t < 128; t++) {
            float qv[4], kv[4];
            #pragma unroll
            for (int i = 0; i < 4; i++) qv[i] = qs[(c0 + i)*512 + jj];
            #pragma unroll
            for (int i = 0; i < 4; i++) kv[i] = ks[(d0 + i)*512 + jj];
            #pragma unroll
            for (int i = 0; i < 4; i++)
                #pragma unroll
                for (int l = 0; l < 4; l++) acc[i][l] += qv[i]*kv[l];
            jj = (jj + 4) & 511;
        }
        #pragma unroll
        for (int i = 0; i < 4; i++)
            #pragma unroll
            for (int l = 0; l < 4; l++)
                atomicAdd(&g_S[(size_t)bh*576 + (c0+i)*24 + (d0+l)], acc[i][l]);
    }
    __syncthreads();
    if (tid < 48) {
        int gi = (tid < 24) ? (b*384 + h*24 + tid) : (b*384 + 192 + h*24 + (tid - 24));
        atomicAdd(&g_norm[gi], snorm[tid]);
    }
}

// ---------------- softmax + M = Wproj @ blockdiag(attn) ----------------
__global__ __launch_bounds__(192) void k_soft(const float* __restrict__ temp,
                                              const float* __restrict__ resc,
                                              const float* __restrict__ wproj)
{
    __shared__ float a[24][24];
    const int h = blockIdx.x, b = blockIdx.y;
    const int tid = threadIdx.x;
    const float* Sp = g_S + (size_t)(b*8 + h) * 576;
    const float t = temp[h];
    for (int idx = tid; idx < 576; idx += 192) {
        int c = idx / 24, d = idx % 24;
        float nq = sqrtf(g_norm[b*384 + h*24 + c]);
        float nk = sqrtf(g_norm[b*384 + 192 + h*24 + d]);
        float denom = fmaxf(nq, 1e-12f) * fmaxf(nk, 1e-12f);
        float l = Sp[idx] / denom * t;
        if (c == d) l += resc[h] * g_var[b*192 + h*24 + c];
        a[c][d] = l;
    }
    __syncthreads();
    if (tid < 24) {
        const int c = tid;
        float m = -1e30f;
        #pragma unroll
        for (int d = 0; d < 24; d++) m = fmaxf(m, a[c][d]);
        float e[24]; float ssum = 0.f;
        #pragma unroll
        for (int d = 0; d < 24; d++) { e[d] = expf(a[c][d] - m); ssum += e[d]; }
        float inv = 1.f / ssum;
        #pragma unroll
        for (int d = 0; d < 24; d++) a[c][d] = e[d] * inv;
    }
    __syncthreads();
    const int co = tid;
    float wr[24];
    #pragma unroll
    for (int c = 0; c < 24; c++) wr[c] = wproj[(size_t)co*CDIM + h*24 + c];
    float* Mp = g_M + (size_t)b*CDIM*CDIM + (size_t)co*CDIM + h*24;
    #pragma unroll 4
    for (int d = 0; d < 24; d++) {
        float accv = 0.f;
        #pragma unroll
        for (int c = 0; c < 24; c++) accv += wr[c] * a[c][d];
        Mp[d] = accv;
    }
}

// ---------------- launch ----------------
extern "C" void kernel_launch(void* const* d_in, const int* in_sizes, int n_in,
                              void* d_out, int out_size)
{
    const float* x       = (const float*)d_in[0];
    const float* w_dw    = (const float*)d_in[1];
    const float* w_qkv   = (const float*)d_in[2];
    const float* w_qkvdw = (const float*)d_in[3];
    const float* w_proj  = (const float*)d_in[4];
    const float* temp    = (const float*)d_in[5];
    const float* resc    = (const float*)d_in[6];
    float* out = (float*)d_out;

    float *qkvp, *vp, *Mp;
    cudaGetSymbolAddress((void**)&qkvp, g_qkv);
    cudaGetSymbolAddress((void**)&vp,   g_v);
    cudaGetSymbolAddress((void**)&Mp,   g_M);

    const int QKS_SMEM = 25840 * 4;   // 103,360 B
    cudaFuncSetAttribute(k_qks, cudaFuncAttributeMaxDynamicSharedMemorySize, QKS_SMEM);
    cudaFuncSetAttribute(gemm_mma, cudaFuncAttributePreferredSharedMemoryCarveout, 90);

    k_zero<<<40, 1024>>>();
    k_dw_var<<<BATCH*CDIM, 256>>>(x, w_dw);
    // qkv 1x1 conv: per batch [576,16384] = W[576,192] @ x[b][192,16384]
    gemm_mma<<<dim3(64, 9, BATCH), 256>>>(w_qkv, x, qkvp,
        C3, HW, CDIM, 0LL, (long long)CDIM*HW, (long long)C3*HW);
    k_dwv<<<BATCH*CDIM, 256>>>(w_qkvdw);
    k_qks<<<dim3(64, 32), 256, QKS_SMEM>>>(w_qkvdw);
    k_soft<<<dim3(HEADS, BATCH), 192>>>(temp, resc, w_proj);
    // final: out[b] = M[b](192x192) @ V[b](192x16384)
    gemm_mma<<<dim3(64, 3, BATCH), 256>>>(Mp, vp, out,
        CDIM, HW, CDIM, (long long)CDIM*CDIM, (long long)CDIM*HW, (long long)CDIM*HW);
}

// round 5
// speedup vs baseline: 1.7573x; 1.7573x over previous
#include <cuda_runtime.h>
#include <cuda_bf16.h>
#include <cstdint>

#define HW   16384
#define CDIM 192
#define C3   576
#define BATCH 8
#define HEADS 8
#define CHD  24

// ---------------- scratch (device globals: allocation-free rule) ----------------
__device__ float g_qkv [75497472];            // [8,576,16384] after 1x1 conv
__device__ __nv_bfloat16 g_qk[50331648];      // [8,384,16384] dw-conv'd q,k in bf16
__device__ float g_v   [25165824];            // [8,192,16384] dw-conv'd v (fp32)
__device__ float g_var [BATCH*CDIM];
__device__ float g_norm[BATCH*384];           // sumsq of bf16 q (0..191) / k (192..383)
__device__ float g_S   [BATCH*HEADS*CHD*CHD];
__device__ float g_M   [BATCH*CDIM*CDIM];

__device__ __forceinline__ uint32_t smem_u32(const void* p) {
    uint32_t a;
    asm("{ .reg .u64 t; cvta.to.shared.u64 t, %1; cvt.u32.u64 %0, t; }" : "=r"(a) : "l"(p));
    return a;
}
__device__ __forceinline__ uint32_t f2tf32(float f) {
    uint32_t o;
    asm("cvt.rna.tf32.f32 %0, %1;" : "=r"(o) : "f"(f));
    return o;
}
__device__ __forceinline__ void mma_tf32(float* c, const uint32_t* a, const uint32_t* b) {
    asm volatile(
        "mma.sync.aligned.m16n8k8.row.col.f32.tf32.tf32.f32 "
        "{%0,%1,%2,%3}, {%4,%5,%6,%7}, {%8,%9}, {%0,%1,%2,%3};"
        : "+f"(c[0]), "+f"(c[1]), "+f"(c[2]), "+f"(c[3])
        : "r"(a[0]), "r"(a[1]), "r"(a[2]), "r"(a[3]), "r"(b[0]), "r"(b[1]));
}
__device__ __forceinline__ void cp_async16(uint32_t dst, const void* src) {
    asm volatile("cp.async.cg.shared.global [%0], [%1], 16;" :: "r"(dst), "l"(src) : "memory");
}

// ================= tf32 mma.sync batched GEMM: C[M,N] = A[M,K] @ B[K,N] =================
// BM=64 (blockIdx.x -> all m-tiles of one n-column adjacent => B slab L2 reuse), BN=256.
__global__ void __launch_bounds__(256, 2) gemm_mma(
    const float* __restrict__ A, const float* __restrict__ B, float* __restrict__ C,
    int M, int N, int K, long long sA, long long sB, long long sC)
{
    __shared__ float As[2][16][72];
    __shared__ float Bs[2][16][264];
    const int tid  = threadIdx.x;
    const int lane = tid & 31;
    const int wid  = tid >> 5;
    const int g    = lane >> 2;
    const int t    = lane & 3;
    const float* Ab = A + (long long)blockIdx.z * sA;
    const float* Bb = B + (long long)blockIdx.z * sB;
    float*       Cb = C + (long long)blockIdx.z * sC;
    const int bm = blockIdx.x * 64;     // m fast dim
    const int bn = blockIdx.y * 256;    // n slow dim

    const int am    = tid & 63;
    const int ak    = (tid >> 6) << 2;
    const int bnoff = (tid & 63) << 2;
    const int bk    = tid >> 6;

    float acc[4][4][4];
    #pragma unroll
    for (int i = 0; i < 4; i++)
        #pragma unroll
        for (int j = 0; j < 4; j++)
            #pragma unroll
            for (int l = 0; l < 4; l++) acc[i][j][l] = 0.f;

    float4 areg = *(const float4*)&Ab[(size_t)(bm + am) * K + ak];
    #pragma unroll
    for (int p = 0; p < 4; p++)
        cp_async16(smem_u32(&Bs[0][bk + p * 4][bnoff]),
                   &Bb[(size_t)(bk + p * 4) * N + bn + bnoff]);
    asm volatile("cp.async.commit_group;" ::: "memory");
    As[0][ak + 0][am] = __uint_as_float(f2tf32(areg.x));
    As[0][ak + 1][am] = __uint_as_float(f2tf32(areg.y));
    As[0][ak + 2][am] = __uint_as_float(f2tf32(areg.z));
    As[0][ak + 3][am] = __uint_as_float(f2tf32(areg.w));
    asm volatile("cp.async.wait_group 0;" ::: "memory");
    __syncthreads();

    const int nk = K >> 4;
    for (int i = 0; i < nk; i++) {
        const int s = i & 1;
        float4 anext;
        if (i + 1 < nk) {
            const int k0 = (i + 1) << 4;
            anext = *(const float4*)&Ab[(size_t)(bm + am) * K + k0 + ak];
            #pragma unroll
            for (int p = 0; p < 4; p++)
                cp_async16(smem_u32(&Bs[s ^ 1][bk + p * 4][bnoff]),
                           &Bb[(size_t)(k0 + bk + p * 4) * N + bn + bnoff]);
            asm volatile("cp.async.commit_group;" ::: "memory");
        }
        #pragma unroll
        for (int kk = 0; kk < 2; kk++) {
            uint32_t af[4][4];
            #pragma unroll
            for (int ma = 0; ma < 4; ma++) {
                af[ma][0] = __float_as_uint(As[s][kk * 8 + t    ][ma * 16 + g    ]);
                af[ma][1] = __float_as_uint(As[s][kk * 8 + t    ][ma * 16 + g + 8]);
                af[ma][2] = __float_as_uint(As[s][kk * 8 + t + 4][ma * 16 + g    ]);
                af[ma][3] = __float_as_uint(As[s][kk * 8 + t + 4][ma * 16 + g + 8]);
            }
            uint32_t bf[4][2];
            #pragma unroll
            for (int na = 0; na < 4; na++) {
                bf[na][0] = f2tf32(Bs[s][kk * 8 + t    ][wid * 32 + na * 8 + g]);
                bf[na][1] = f2tf32(Bs[s][kk * 8 + t + 4][wid * 32 + na * 8 + g]);
            }
            #pragma unroll
            for (int ma = 0; ma < 4; ma++)
                #pragma unroll
                for (int na = 0; na < 4; na++)
                    mma_tf32(acc[ma][na], af[ma], bf[na]);
        }
        if (i + 1 < nk) {
            As[s ^ 1][ak + 0][am] = __uint_as_float(f2tf32(anext.x));
            As[s ^ 1][ak + 1][am] = __uint_as_float(f2tf32(anext.y));
            As[s ^ 1][ak + 2][am] = __uint_as_float(f2tf32(anext.z));
            As[s ^ 1][ak + 3][am] = __uint_as_float(f2tf32(anext.w));
            asm volatile("cp.async.wait_group 0;" ::: "memory");
        }
        __syncthreads();
    }
    #pragma unroll
    for (int ma = 0; ma < 4; ma++) {
        #pragma unroll
        for (int na = 0; na < 4; na++) {
            const int row = bm + ma * 16 + g;
            const int col = bn + wid * 32 + na * 8 + (t << 1);
            *(float2*)&Cb[(size_t)row * N + col]       = make_float2(acc[ma][na][0], acc[ma][na][1]);
            *(float2*)&Cb[(size_t)(row + 8) * N + col] = make_float2(acc[ma][na][2], acc[ma][na][3]);
        }
    }
}

// ---------------- zero the split-K S accumulator ----------------
__global__ void k_zero() {
    int i = blockIdx.x * blockDim.x + threadIdx.x;
    if (i < BATCH*HEADS*CHD*CHD) g_S[i] = 0.f;
}

// ---------------- depthwise 3x3 on x + unbiased variance, 4px/thread ----------------
__global__ __launch_bounds__(256) void k_dw_var(const float* __restrict__ x,
                                                const float* __restrict__ wdw)
{
    __shared__ float s[66*132];
    __shared__ float red[64];
    const int bc = blockIdx.x;
    const float* plane = x + (size_t)bc * HW;
    const int c = bc % CDIM;
    const int tid = threadIdx.x;
    float w9[9];
    #pragma unroll
    for (int i = 0; i < 9; i++) w9[i] = wdw[c*9 + i];
    float sum = 0.f, sq = 0.f;
    for (int half = 0; half < 2; half++) {
        if (half) __syncthreads();
        const int y0 = half * 64;
        for (int i = tid; i < 66*132; i += 256) {
            int r = i / 132, cc = i % 132;
            int y = y0 + r - 1, xx = cc - 1;
            s[i] = (cc < 130 && y >= 0 && y < 128 && (unsigned)xx < 128u) ? plane[y*128 + xx] : 0.f;
        }
        __syncthreads();
        for (int p = tid; p < 2048; p += 256) {
            int yl = p >> 5, x4 = (p & 31) << 2;
            const float* bp = &s[yl*132 + x4];
            float4 a0 = *(const float4*)bp,        a1 = *(const float4*)(bp + 4);
            float4 b0 = *(const float4*)(bp+132),  b1 = *(const float4*)(bp + 136);
            float4 c0 = *(const float4*)(bp+264),  c1 = *(const float4*)(bp + 268);
            float r0[6] = {a0.x,a0.y,a0.z,a0.w,a1.x,a1.y};
            float r1[6] = {b0.x,b0.y,b0.z,b0.w,b1.x,b1.y};
            float r2[6] = {c0.x,c0.y,c0.z,c0.w,c1.x,c1.y};
            #pragma unroll
            for (int i = 0; i < 4; i++) {
                float v = r0[i]*w9[0] + r0[i+1]*w9[1] + r0[i+2]*w9[2]
                        + r1[i]*w9[3] + r1[i+1]*w9[4] + r1[i+2]*w9[5]
                        + r2[i]*w9[6] + r2[i+1]*w9[7] + r2[i+2]*w9[8];
                sum += v; sq += v*v;
            }
        }
    }
    #pragma unroll
    for (int o = 16; o > 0; o >>= 1) {
        sum += __shfl_down_sync(0xffffffffu, sum, o);
        sq  += __shfl_down_sync(0xffffffffu, sq,  o);
    }
    if ((tid & 31) == 0) { red[tid>>5] = sum; red[32 + (tid>>5)] = sq; }
    __syncthreads();
    if (tid == 0) {
        float S = 0.f, Q = 0.f;
        #pragma unroll
        for (int i = 0; i < 8; i++) { S += red[i]; Q += red[32+i]; }
        g_var[bc] = (Q - S*S*(1.f/16384.f)) * (1.f/16383.f);
    }
}

// ---------------- depthwise 3x3 on qkv: q,k -> bf16 (+norms), v -> fp32 ----------------
__global__ __launch_bounds__(256) void k_dw_qkv(const float* __restrict__ wdw)
{
    __shared__ float s[66*132];
    __shared__ float red[8];
    const int bc = blockIdx.x;                  // b*576 + ch
    const int ch = bc % C3;
    const int b  = bc / C3;
    const float* plane = g_qkv + (size_t)bc * HW;
    const bool is_qk = ch < 384;
    __nv_bfloat16* outb = g_qk + ((size_t)b*384 + ch) * HW;
    float*         outv = g_v  + ((size_t)b*CDIM + (ch - 384)) * HW;
    const int tid = threadIdx.x;
    float w9[9];
    #pragma unroll
    for (int i = 0; i < 9; i++) w9[i] = wdw[ch*9 + i];
    float sq = 0.f;
    for (int half = 0; half < 2; half++) {
        if (half) __syncthreads();
        const int y0 = half * 64;
        for (int i = tid; i < 66*132; i += 256) {
            int r = i / 132, cc = i % 132;
            int y = y0 + r - 1, xx = cc - 1;
            s[i] = (cc < 130 && y >= 0 && y < 128 && (unsigned)xx < 128u) ? plane[y*128 + xx] : 0.f;
        }
        __syncthreads();
        for (int p = tid; p < 2048; p += 256) {
            int yl = p >> 5, x4 = (p & 31) << 2;
            const float* bp = &s[yl*132 + x4];
            float4 a0 = *(const float4*)bp,        a1 = *(const float4*)(bp + 4);
            float4 b0 = *(const float4*)(bp+132),  b1 = *(const float4*)(bp + 136);
            float4 c0 = *(const float4*)(bp+264),  c1 = *(const float4*)(bp + 268);
            float r0[6] = {a0.x,a0.y,a0.z,a0.w,a1.x,a1.y};
            float r1[6] = {b0.x,b0.y,b0.z,b0.w,b1.x,b1.y};
            float r2[6] = {c0.x,c0.y,c0.z,c0.w,c1.x,c1.y};
            float ov[4];
            #pragma unroll
            for (int i = 0; i < 4; i++)
                ov[i] = r0[i]*w9[0] + r0[i+1]*w9[1] + r0[i+2]*w9[2]
                      + r1[i]*w9[3] + r1[i+1]*w9[4] + r1[i+2]*w9[5]
                      + r2[i]*w9[6] + r2[i+1]*w9[7] + r2[i+2]*w9[8];
            const int idx = (y0 + yl)*128 + x4;
            if (is_qk) {
                __nv_bfloat162 p0 = __floats2bfloat162_rn(ov[0], ov[1]);
                __nv_bfloat162 p1 = __floats2bfloat162_rn(ov[2], ov[3]);
                // norms from the SAME rounded values (consistent normalization)
                float f0 = __bfloat162float(p0.x), f1 = __bfloat162float(p0.y);
                float f2 = __bfloat162float(p1.x), f3 = __bfloat162float(p1.y);
                sq += f0*f0 + f1*f1 + f2*f2 + f3*f3;
                uint2 u;
                u.x = *(uint32_t*)&p0; u.y = *(uint32_t*)&p1;
                *(uint2*)&outb[idx] = u;
            } else {
                float4 o; o.x = ov[0]; o.y = ov[1]; o.z = ov[2]; o.w = ov[3];
                *(float4*)&outv[idx] = o;
            }
        }
    }
    if (is_qk) {
        #pragma unroll
        for (int o = 16; o > 0; o >>= 1) sq += __shfl_down_sync(0xffffffffu, sq, o);
        if ((tid & 31) == 0) red[tid>>5] = sq;
        __syncthreads();
        if (tid == 0) {
            float Q = 0.f;
            #pragma unroll
            for (int i = 0; i < 8; i++) Q += red[i];
            g_norm[b*384 + ch] = Q;
        }
    }
}

// ---------------- S = q @ k^T per (b,h) from bf16, split-K with atomics ----------------
__global__ __launch_bounds__(144) void k_qk()
{
    __shared__ float qs[24][64];
    __shared__ float ks[24][64];
    const int bh = blockIdx.x;
    const int b = bh >> 3, h = bh & 7;
    const __nv_bfloat16* qb = g_qk + ((size_t)b*384 + h*CHD) * HW;
    const __nv_bfloat16* kb = g_qk + ((size_t)b*384 + 192 + h*CHD) * HW;
    const int n0 = blockIdx.y * 1024;
    const int tid = threadIdx.x;
    const int sub = tid & 3;
    const int cd  = tid >> 2;
    const int c0 = (cd / 6) * 4, d0 = (cd % 6) * 4;
    float acc[4][4] = {};
    for (int chk = 0; chk < 16; chk++) {
        if (chk) __syncthreads();
        const int nn = n0 + chk * 64;
        for (int i = tid; i < 24*32; i += 144) {
            int r = i >> 5, j2 = (i & 31) << 1;
            __nv_bfloat162 q2 = *(const __nv_bfloat162*)&qb[(size_t)r*HW + nn + j2];
            __nv_bfloat162 k2 = *(const __nv_bfloat162*)&kb[(size_t)r*HW + nn + j2];
            *(float2*)&qs[r][j2] = make_float2(__bfloat162float(q2.x), __bfloat162float(q2.y));
            *(float2*)&ks[r][j2] = make_float2(__bfloat162float(k2.x), __bfloat162float(k2.y));
        }
        __syncthreads();
        const int j0 = sub * 16;
        #pragma unroll 4
        for (int j = j0; j < j0 + 16; j++) {
            float q0 = qs[c0+0][j], q1 = qs[c0+1][j], q2 = qs[c0+2][j], q3 = qs[c0+3][j];
            float k0 = ks[d0+0][j], k1 = ks[d0+1][j], k2 = ks[d0+2][j], k3 = ks[d0+3][j];
            acc[0][0] += q0*k0; acc[0][1] += q0*k1; acc[0][2] += q0*k2; acc[0][3] += q0*k3;
            acc[1][0] += q1*k0; acc[1][1] += q1*k1; acc[1][2] += q1*k2; acc[1][3] += q1*k3;
            acc[2][0] += q2*k0; acc[2][1] += q2*k1; acc[2][2] += q2*k2; acc[2][3] += q2*k3;
            acc[3][0] += q3*k0; acc[3][1] += q3*k1; acc[3][2] += q3*k2; acc[3][3] += q3*k3;
        }
    }
    #pragma unroll
    for (int i = 0; i < 4; i++)
        #pragma unroll
        for (int l = 0; l < 4; l++)
            atomicAdd(&g_S[(size_t)bh*576 + (c0+i)*24 + (d0+l)], acc[i][l]);
}

// ---------------- softmax + M = Wproj @ blockdiag(attn) ----------------
__global__ __launch_bounds__(192) void k_soft(const float* __restrict__ temp,
                                              const float* __restrict__ resc,
                                              const float* __restrict__ wproj)
{
    __shared__ float a[24][24];
    const int h = blockIdx.x, b = blockIdx.y;
    const int tid = threadIdx.x;
    const float* Sp = g_S + (size_t)(b*8 + h) * 576;
    const float t = temp[h];
    for (int idx = tid; idx < 576; idx += 192) {
        int c = idx / 24, d = idx % 24;
        float nq = sqrtf(g_norm[b*384 + h*24 + c]);
        float nk = sqrtf(g_norm[b*384 + 192 + h*24 + d]);
        float denom = fmaxf(nq, 1e-12f) * fmaxf(nk, 1e-12f);
        float l = Sp[idx] / denom * t;
        if (c == d) l += resc[h] * g_var[b*192 + h*24 + c];
        a[c][d] = l;
    }
    __syncthreads();
    if (tid < 24) {
        const int c = tid;
        float m = -1e30f;
        #pragma unroll
        for (int d = 0; d < 24; d++) m = fmaxf(m, a[c][d]);
        float e[24]; float ssum = 0.f;
        #pragma unroll
        for (int d = 0; d < 24; d++) { e[d] = expf(a[c][d] - m); ssum += e[d]; }
        float inv = 1.f / ssum;
        #pragma unroll
        for (int d = 0; d < 24; d++) a[c][d] = e[d] * inv;
    }
    __syncthreads();
    const int co = tid;
    float wr[24];
    #pragma unroll
    for (int c = 0; c < 24; c++) wr[c] = wproj[(size_t)co*CDIM + h*24 + c];
    float* Mp = g_M + (size_t)b*CDIM*CDIM + (size_t)co*CDIM + h*24;
    #pragma unroll 4
    for (int d = 0; d < 24; d++) {
        float accv = 0.f;
        #pragma unroll
        for (int c = 0; c < 24; c++) accv += wr[c] * a[c][d];
        Mp[d] = accv;
    }
}

// ---------------- launch ----------------
extern "C" void kernel_launch(void* const* d_in, const int* in_sizes, int n_in,
                              void* d_out, int out_size)
{
    const float* x       = (const float*)d_in[0];
    const float* w_dw    = (const float*)d_in[1];
    const float* w_qkv   = (const float*)d_in[2];
    const float* w_qkvdw = (const float*)d_in[3];
    const float* w_proj  = (const float*)d_in[4];
    const float* temp    = (const float*)d_in[5];
    const float* resc    = (const float*)d_in[6];
    float* out = (float*)d_out;

    float *qkvp, *vp, *Mp;
    cudaGetSymbolAddress((void**)&qkvp, g_qkv);
    cudaGetSymbolAddress((void**)&vp,   g_v);
    cudaGetSymbolAddress((void**)&Mp,   g_M);

    cudaFuncSetAttribute(gemm_mma, cudaFuncAttributePreferredSharedMemoryCarveout, 90);

    k_zero<<<36, 1024>>>();
    k_dw_var<<<BATCH*CDIM, 256>>>(x, w_dw);
    // qkv 1x1 conv: per batch [576,16384] = W[576,192] @ x[b][192,16384]
    gemm_mma<<<dim3(9, 64, BATCH), 256>>>(w_qkv, x, qkvp,
        C3, HW, CDIM, 0LL, (long long)CDIM*HW, (long long)C3*HW);
    k_dw_qkv<<<BATCH*C3, 256>>>(w_qkvdw);
    k_qk<<<dim3(64, 16), 144>>>();
    k_soft<<<dim3(HEADS, BATCH), 192>>>(temp, resc, w_proj);
    // final: out[b] = M[b](192x192) @ V[b](192x16384)
    gemm_mma<<<dim3(3, 64, BATCH), 256>>>(Mp, vp, out,
        CDIM, HW, CDIM, (long long)CDIM*CDIM, (long long)CDIM*HW, (long long)CDIM*HW);
}

// round 6
// speedup vs baseline: 1.9710x; 1.1216x over previous
#include <cuda_runtime.h>
#include <cuda_bf16.h>
#include <cstdint>

#define HW   16384
#define CDIM 192
#define C3   576
#define BATCH 8
#define HEADS 8
#define CHD  24

typedef unsigned long long ull;

// ---------------- scratch (device globals: allocation-free rule) ----------------
__device__ __nv_bfloat16 g_qkb[50331648];   // [8,384,16384] pre-conv q,k (bf16, gemm1 out)
__device__ float g_vpre[25165824];          // [8,192,16384] pre-conv v (fp32, gemm1 out)
__device__ __nv_bfloat16 g_qk[50331648];    // [8,384,16384] post-conv q,k (bf16)
__device__ float g_v  [25165824];           // [8,192,16384] post-conv v (fp32)
__device__ float g_var [BATCH*CDIM];
__device__ float g_norm[BATCH*384];
__device__ float g_S   [BATCH*HEADS*CHD*CHD];
__device__ float g_M   [BATCH*CDIM*CDIM];

__device__ __forceinline__ uint32_t smem_u32(const void* p) {
    uint32_t a;
    asm("{ .reg .u64 t; cvta.to.shared.u64 t, %1; cvt.u32.u64 %0, t; }" : "=r"(a) : "l"(p));
    return a;
}
__device__ __forceinline__ uint32_t f2tf32(float f) {
    uint32_t o;
    asm("cvt.rna.tf32.f32 %0, %1;" : "=r"(o) : "f"(f));
    return o;
}
__device__ __forceinline__ void mma_tf32(float* c, const uint32_t* a, const uint32_t* b) {
    asm volatile(
        "mma.sync.aligned.m16n8k8.row.col.f32.tf32.tf32.f32 "
        "{%0,%1,%2,%3}, {%4,%5,%6,%7}, {%8,%9}, {%0,%1,%2,%3};"
        : "+f"(c[0]), "+f"(c[1]), "+f"(c[2]), "+f"(c[3])
        : "r"(a[0]), "r"(a[1]), "r"(a[2]), "r"(a[3]), "r"(b[0]), "r"(b[1]));
}
__device__ __forceinline__ void cp_async16(uint32_t dst, const void* src) {
    asm volatile("cp.async.cg.shared.global [%0], [%1], 16;" :: "r"(dst), "l"(src) : "memory");
}
__device__ __forceinline__ ull pack2(float a, float b) {
    ull r; asm("mov.b64 %0, {%1,%2};" : "=l"(r) : "f"(a), "f"(b)); return r;
}
__device__ __forceinline__ void ffma2(ull& acc, ull a, ull b) {
    asm("fma.rn.f32x2 %0, %1, %2, %0;" : "+l"(acc) : "l"(a), "l"(b));
}
__device__ __forceinline__ void add2(ull& acc, ull a) {
    asm("add.rn.f32x2 %0, %0, %1;" : "+l"(acc) : "l"(a));
}
__device__ __forceinline__ float2 unpack2(ull v) {
    float2 o; asm("mov.b64 {%0,%1}, %2;" : "=f"(o.x), "=f"(o.y) : "l"(v)); return o;
}

// ================= tf32 mma.sync batched GEMM (mixed epilogue for gemm1) =================
// C[M,N] = A[M,K] @ B[K,N]. If C16 != null: rows < 384 -> bf16 into C16, rows >= 384 ->
// fp32 into C at (row-384). Blocks are 64-row aligned; 384 % 64 == 0 so class is uniform.
__global__ void __launch_bounds__(256, 2) gemm_mma(
    const float* __restrict__ A, const float* __restrict__ B, float* __restrict__ C,
    __nv_bfloat16* __restrict__ C16,
    int M, int N, int K, long long sA, long long sB, long long sC, long long sC16)
{
    __shared__ float As[2][16][72];
    __shared__ float Bs[2][16][264];
    const int tid  = threadIdx.x;
    const int lane = tid & 31;
    const int wid  = tid >> 5;
    const int g    = lane >> 2;
    const int t    = lane & 3;
    const float* Ab = A + (long long)blockIdx.z * sA;
    const float* Bb = B + (long long)blockIdx.z * sB;
    const int bm = blockIdx.x * 64;
    const int bn = blockIdx.y * 256;

    const int am    = tid & 63;
    const int ak    = (tid >> 6) << 2;
    const int bnoff = (tid & 63) << 2;
    const int bk    = tid >> 6;

    float acc[4][4][4];
    #pragma unroll
    for (int i = 0; i < 4; i++)
        #pragma unroll
        for (int j = 0; j < 4; j++)
            #pragma unroll
            for (int l = 0; l < 4; l++) acc[i][j][l] = 0.f;

    float4 areg = *(const float4*)&Ab[(size_t)(bm + am) * K + ak];
    #pragma unroll
    for (int p = 0; p < 4; p++)
        cp_async16(smem_u32(&Bs[0][bk + p * 4][bnoff]),
                   &Bb[(size_t)(bk + p * 4) * N + bn + bnoff]);
    asm volatile("cp.async.commit_group;" ::: "memory");
    As[0][ak + 0][am] = __uint_as_float(f2tf32(areg.x));
    As[0][ak + 1][am] = __uint_as_float(f2tf32(areg.y));
    As[0][ak + 2][am] = __uint_as_float(f2tf32(areg.z));
    As[0][ak + 3][am] = __uint_as_float(f2tf32(areg.w));
    asm volatile("cp.async.wait_group 0;" ::: "memory");
    __syncthreads();

    const int nk = K >> 4;
    for (int i = 0; i < nk; i++) {
        const int s = i & 1;
        float4 anext;
        if (i + 1 < nk) {
            const int k0 = (i + 1) << 4;
            anext = *(const float4*)&Ab[(size_t)(bm + am) * K + k0 + ak];
            #pragma unroll
            for (int p = 0; p < 4; p++)
                cp_async16(smem_u32(&Bs[s ^ 1][bk + p * 4][bnoff]),
                           &Bb[(size_t)(k0 + bk + p * 4) * N + bn + bnoff]);
            asm volatile("cp.async.commit_group;" ::: "memory");
        }
        #pragma unroll
        for (int kk = 0; kk < 2; kk++) {
            uint32_t af[4][4];
            #pragma unroll
            for (int ma = 0; ma < 4; ma++) {
                af[ma][0] = __float_as_uint(As[s][kk * 8 + t    ][ma * 16 + g    ]);
                af[ma][1] = __float_as_uint(As[s][kk * 8 + t    ][ma * 16 + g + 8]);
                af[ma][2] = __float_as_uint(As[s][kk * 8 + t + 4][ma * 16 + g    ]);
                af[ma][3] = __float_as_uint(As[s][kk * 8 + t + 4][ma * 16 + g + 8]);
            }
            uint32_t bf[4][2];
            #pragma unroll
            for (int na = 0; na < 4; na++) {
                bf[na][0] = f2tf32(Bs[s][kk * 8 + t    ][wid * 32 + na * 8 + g]);
                bf[na][1] = f2tf32(Bs[s][kk * 8 + t + 4][wid * 32 + na * 8 + g]);
            }
            #pragma unroll
            for (int ma = 0; ma < 4; ma++)
                #pragma unroll
                for (int na = 0; na < 4; na++)
                    mma_tf32(acc[ma][na], af[ma], bf[na]);
        }
        if (i + 1 < nk) {
            As[s ^ 1][ak + 0][am] = __uint_as_float(f2tf32(anext.x));
            As[s ^ 1][ak + 1][am] = __uint_as_float(f2tf32(anext.y));
            As[s ^ 1][ak + 2][am] = __uint_as_float(f2tf32(anext.z));
            As[s ^ 1][ak + 3][am] = __uint_as_float(f2tf32(anext.w));
            asm volatile("cp.async.wait_group 0;" ::: "memory");
        }
        __syncthreads();
    }
    const bool bfout = (C16 != nullptr) && (bm < 384);
    if (bfout) {
        __nv_bfloat16* Cb16 = C16 + (long long)blockIdx.z * sC16;
        #pragma unroll
        for (int ma = 0; ma < 4; ma++) {
            #pragma unroll
            for (int na = 0; na < 4; na++) {
                const int row = bm + ma * 16 + g;
                const int col = bn + wid * 32 + na * 8 + (t << 1);
                __nv_bfloat162 h0 = __floats2bfloat162_rn(acc[ma][na][0], acc[ma][na][1]);
                __nv_bfloat162 h1 = __floats2bfloat162_rn(acc[ma][na][2], acc[ma][na][3]);
                *(__nv_bfloat162*)&Cb16[(size_t)row * N + col]       = h0;
                *(__nv_bfloat162*)&Cb16[(size_t)(row + 8) * N + col] = h1;
            }
        }
    } else {
        const int radj = (C16 != nullptr) ? 384 : 0;
        float* Cb = C + (long long)blockIdx.z * sC;
        #pragma unroll
        for (int ma = 0; ma < 4; ma++) {
            #pragma unroll
            for (int na = 0; na < 4; na++) {
                const int row = bm + ma * 16 + g - radj;
                const int col = bn + wid * 32 + na * 8 + (t << 1);
                *(float2*)&Cb[(size_t)row * N + col]       = make_float2(acc[ma][na][0], acc[ma][na][1]);
                *(float2*)&Cb[(size_t)(row + 8) * N + col] = make_float2(acc[ma][na][2], acc[ma][na][3]);
            }
        }
    }
}

__global__ void k_zero() {
    int i = blockIdx.x * blockDim.x + threadIdx.x;
    if (i < BATCH*HEADS*CHD*CHD) g_S[i] = 0.f;
}

// =============== rolling-window f32x2 depthwise 3x3 core pieces ===============
// SMEM tile: 66 rows x 132 cols. smem row r holds image row (y0 + r - 1); image col x
// at smem col x; cols 128..129 zero. Thread: col-group cg = lane (4 cols), strip = warp.

__device__ __forceinline__ void conv_loadP(const float* s, int sr, int x4, int lane, ull* P) {
    const float* rp = &s[sr * 132 + x4];
    float4 q = *(const float4*)rp;
    float rx = rp[4];
    float lf = __shfl_up_sync(0xffffffffu, q.w, 1);
    if (lane == 0) lf = 0.f;
    P[0] = pack2(lf,  q.x);
    P[1] = pack2(q.x, q.y);
    P[2] = pack2(q.y, q.z);
    P[3] = pack2(q.z, q.w);
    P[4] = pack2(q.w, rx);
}

#define CONV_ACC(a01, a23, P, o, Wp)                                        \
    {                                                                        \
        _Pragma("unroll")                                                    \
        for (int r = 0; r < 3; r++) {                                        \
            const ull* Q = P[((o) + r) % 3];                                 \
            ffma2(a01, Q[0], Wp[3*r+0]); ffma2(a01, Q[1], Wp[3*r+1]);        \
            ffma2(a01, Q[2], Wp[3*r+2]);                                     \
            ffma2(a23, Q[2], Wp[3*r+0]); ffma2(a23, Q[3], Wp[3*r+1]);        \
            ffma2(a23, Q[4], Wp[3*r+2]);                                     \
        }                                                                    \
    }

// ---------------- depthwise 3x3 on x + unbiased variance ----------------
__global__ __launch_bounds__(256) void k_dw_var(const float* __restrict__ x,
                                                const float* __restrict__ wdw)
{
    __shared__ float s[66*132];
    __shared__ float red[64];
    const int bc = blockIdx.x;
    const float* plane = x + (size_t)bc * HW;
    const int c = bc % CDIM;
    const int tid = threadIdx.x;
    const int lane = tid & 31;
    const int strip = tid >> 5;
    const int x4 = lane << 2;
    ull Wp[9];
    #pragma unroll
    for (int i = 0; i < 9; i++) { float w = wdw[c*9 + i]; Wp[i] = pack2(w, w); }
    ull accS = 0ull, accQ = 0ull;

    for (int half = 0; half < 2; half++) {
        if (half) __syncthreads();
        const int y0 = half * 64;
        for (int i = tid; i < 66*32; i += 256) {
            int r = i >> 5, j4 = (i & 31) << 2;
            int y = y0 + r - 1;
            float4 v = make_float4(0.f, 0.f, 0.f, 0.f);
            if ((unsigned)y < 128u) v = *(const float4*)&plane[y*128 + j4];
            *(float4*)&s[r*132 + j4] = v;
        }
        for (int i = tid; i < 66; i += 256) { s[i*132+128] = 0.f; s[i*132+129] = 0.f; }
        __syncthreads();

        ull P[3][5];
        const int base = strip * 8;
        conv_loadP(s, base,     x4, lane, P[0]);
        conv_loadP(s, base + 1, x4, lane, P[1]);
        #pragma unroll
        for (int o = 0; o < 8; o++) {
            conv_loadP(s, base + o + 2, x4, lane, P[(o + 2) % 3]);
            ull a01 = 0ull, a23 = 0ull;
            CONV_ACC(a01, a23, P, o, Wp);
            add2(accS, a01); add2(accS, a23);
            ffma2(accQ, a01, a01); ffma2(accQ, a23, a23);
        }
    }
    float2 S2 = unpack2(accS), Q2 = unpack2(accQ);
    float sum = S2.x + S2.y, sq = Q2.x + Q2.y;
    #pragma unroll
    for (int o = 16; o > 0; o >>= 1) {
        sum += __shfl_down_sync(0xffffffffu, sum, o);
        sq  += __shfl_down_sync(0xffffffffu, sq,  o);
    }
    if (lane == 0) { red[strip] = sum; red[32 + strip] = sq; }
    __syncthreads();
    if (tid == 0) {
        float S = 0.f, Q = 0.f;
        #pragma unroll
        for (int i = 0; i < 8; i++) { S += red[i]; Q += red[32+i]; }
        g_var[bc] = (Q - S*S*(1.f/16384.f)) * (1.f/16383.f);
    }
}

// ---------------- depthwise 3x3 on qkv: q,k bf16->bf16 (+norms), v fp32->fp32 ----------------
__global__ __launch_bounds__(256) void k_dw_qkv(const float* __restrict__ wdw)
{
    __shared__ float s[66*132];
    __shared__ float red[8];
    const int bc = blockIdx.x;                  // b*576 + ch
    const int ch = bc % C3;
    const int b  = bc / C3;
    const bool is_qk = ch < 384;
    const __nv_bfloat16* planeb = g_qkb + ((size_t)b*384 + ch) * HW;
    const float*         planef = g_vpre + ((size_t)b*CDIM + (ch - 384)) * HW;
    __nv_bfloat16* outb = g_qk + ((size_t)b*384 + ch) * HW;
    float*         outv = g_v  + ((size_t)b*CDIM + (ch - 384)) * HW;
    const int tid = threadIdx.x;
    const int lane = tid & 31;
    const int strip = tid >> 5;
    const int x4 = lane << 2;
    ull Wp[9];
    #pragma unroll
    for (int i = 0; i < 9; i++) { float w = wdw[ch*9 + i]; Wp[i] = pack2(w, w); }
    float sq = 0.f;

    for (int half = 0; half < 2; half++) {
        if (half) __syncthreads();
        const int y0 = half * 64;
        if (is_qk) {
            for (int i = tid; i < 66*32; i += 256) {
                int r = i >> 5, j4 = (i & 31) << 2;
                int y = y0 + r - 1;
                float4 v = make_float4(0.f, 0.f, 0.f, 0.f);
                if ((unsigned)y < 128u) {
                    uint2 u = *(const uint2*)&planeb[y*128 + j4];
                    float2 f0 = __bfloat1622float2(*(__nv_bfloat162*)&u.x);
                    float2 f1 = __bfloat1622float2(*(__nv_bfloat162*)&u.y);
                    v = make_float4(f0.x, f0.y, f1.x, f1.y);
                }
                *(float4*)&s[r*132 + j4] = v;
            }
        } else {
            for (int i = tid; i < 66*32; i += 256) {
                int r = i >> 5, j4 = (i & 31) << 2;
                int y = y0 + r - 1;
                float4 v = make_float4(0.f, 0.f, 0.f, 0.f);
                if ((unsigned)y < 128u) v = *(const float4*)&planef[y*128 + j4];
                *(float4*)&s[r*132 + j4] = v;
            }
        }
        for (int i = tid; i < 66; i += 256) { s[i*132+128] = 0.f; s[i*132+129] = 0.f; }
        __syncthreads();

        ull P[3][5];
        const int base = strip * 8;
        conv_loadP(s, base,     x4, lane, P[0]);
        conv_loadP(s, base + 1, x4, lane, P[1]);
        #pragma unroll
        for (int o = 0; o < 8; o++) {
            conv_loadP(s, base + o + 2, x4, lane, P[(o + 2) % 3]);
            ull a01 = 0ull, a23 = 0ull;
            CONV_ACC(a01, a23, P, o, Wp);
            const int y = y0 + base + o;
            float2 v01 = unpack2(a01), v23 = unpack2(a23);
            if (is_qk) {
                __nv_bfloat162 h0 = __floats2bfloat162_rn(v01.x, v01.y);
                __nv_bfloat162 h1 = __floats2bfloat162_rn(v23.x, v23.y);
                uint2 st;
                st.x = *(uint32_t*)&h0; st.y = *(uint32_t*)&h1;
                *(uint2*)&outb[y*128 + x4] = st;
                float2 r0 = __bfloat1622float2(h0), r1 = __bfloat1622float2(h1);
                sq += r0.x*r0.x + r0.y*r0.y + r1.x*r1.x + r1.y*r1.y;
            } else {
                *(float4*)&outv[y*128 + x4] = make_float4(v01.x, v01.y, v23.x, v23.y);
            }
        }
    }
    if (is_qk) {
        #pragma unroll
        for (int o = 16; o > 0; o >>= 1) sq += __shfl_down_sync(0xffffffffu, sq, o);
        if (lane == 0) red[strip] = sq;
        __syncthreads();
        if (tid == 0) {
            float Q = 0.f;
            #pragma unroll
            for (int i = 0; i < 8; i++) Q += red[i];
            g_norm[b*384 + ch] = Q;
        }
    }
}

// ---------------- S = q @ k^T per (b,h) from bf16, split-K with atomics ----------------
__global__ __launch_bounds__(144) void k_qk()
{
    __shared__ float qs[24][64];
    __shared__ float ks[24][64];
    const int bh = blockIdx.x;
    const int b = bh >> 3, h = bh & 7;
    const __nv_bfloat16* qb = g_qk + ((size_t)b*384 + h*CHD) * HW;
    const __nv_bfloat16* kb = g_qk + ((size_t)b*384 + 192 + h*CHD) * HW;
    const int n0 = blockIdx.y * 1024;
    const int tid = threadIdx.x;
    const int sub = tid & 3;
    const int cd  = tid >> 2;
    const int c0 = (cd / 6) * 4, d0 = (cd % 6) * 4;
    float acc[4][4] = {};
    for (int chk = 0; chk < 16; chk++) {
        if (chk) __syncthreads();
        const int nn = n0 + chk * 64;
        for (int i = tid; i < 24*32; i += 144) {
            int r = i >> 5, j2 = (i & 31) << 1;
            __nv_bfloat162 q2 = *(const __nv_bfloat162*)&qb[(size_t)r*HW + nn + j2];
            __nv_bfloat162 k2 = *(const __nv_bfloat162*)&kb[(size_t)r*HW + nn + j2];
            *(float2*)&qs[r][j2] = __bfloat1622float2(q2);
            *(float2*)&ks[r][j2] = __bfloat1622float2(k2);
        }
        __syncthreads();
        const int j0 = sub * 16;
        #pragma unroll 4
        for (int j = j0; j < j0 + 16; j++) {
            float q0 = qs[c0+0][j], q1 = qs[c0+1][j], q2 = qs[c0+2][j], q3 = qs[c0+3][j];
            float k0 = ks[d0+0][j], k1 = ks[d0+1][j], k2 = ks[d0+2][j], k3 = ks[d0+3][j];
            acc[0][0] += q0*k0; acc[0][1] += q0*k1; acc[0][2] += q0*k2; acc[0][3] += q0*k3;
            acc[1][0] += q1*k0; acc[1][1] += q1*k1; acc[1][2] += q1*k2; acc[1][3] += q1*k3;
            acc[2][0] += q2*k0; acc[2][1] += q2*k1; acc[2][2] += q2*k2; acc[2][3] += q2*k3;
            acc[3][0] += q3*k0; acc[3][1] += q3*k1; acc[3][2] += q3*k2; acc[3][3] += q3*k3;
        }
    }
    #pragma unroll
    for (int i = 0; i < 4; i++)
        #pragma unroll
        for (int l = 0; l < 4; l++)
            atomicAdd(&g_S[(size_t)bh*576 + (c0+i)*24 + (d0+l)], acc[i][l]);
}

// ---------------- softmax + M = Wproj @ blockdiag(attn) ----------------
__global__ __launch_bounds__(192) void k_soft(const float* __restrict__ temp,
                                              const float* __restrict__ resc,
                                              const float* __restrict__ wproj)
{
    __shared__ float a[24][24];
    const int h = blockIdx.x, b = blockIdx.y;
    const int tid = threadIdx.x;
    const float* Sp = g_S + (size_t)(b*8 + h) * 576;
    const float t = temp[h];
    for (int idx = tid; idx < 576; idx += 192) {
        int c = idx / 24, d = idx % 24;
        float nq = sqrtf(g_norm[b*384 + h*24 + c]);
        float nk = sqrtf(g_norm[b*384 + 192 + h*24 + d]);
        float denom = fmaxf(nq, 1e-12f) * fmaxf(nk, 1e-12f);
        float l = Sp[idx] / denom * t;
        if (c == d) l += resc[h] * g_var[b*192 + h*24 + c];
        a[c][d] = l;
    }
    __syncthreads();
    if (tid < 24) {
        const int c = tid;
        float m = -1e30f;
        #pragma unroll
        for (int d = 0; d < 24; d++) m = fmaxf(m, a[c][d]);
        float e[24]; float ssum = 0.f;
        #pragma unroll
        for (int d = 0; d < 24; d++) { e[d] = expf(a[c][d] - m); ssum += e[d]; }
        float inv = 1.f / ssum;
        #pragma unroll
        for (int d = 0; d < 24; d++) a[c][d] = e[d] * inv;
    }
    __syncthreads();
    const int co = tid;
    float wr[24];
    #pragma unroll
    for (int c = 0; c < 24; c++) wr[c] = wproj[(size_t)co*CDIM + h*24 + c];
    float* Mp = g_M + (size_t)b*CDIM*CDIM + (size_t)co*CDIM + h*24;
    #pragma unroll 4
    for (int d = 0; d < 24; d++) {
        float accv = 0.f;
        #pragma unroll
        for (int c = 0; c < 24; c++) accv += wr[c] * a[c][d];
        Mp[d] = accv;
    }
}

// ---------------- launch ----------------
extern "C" void kernel_launch(void* const* d_in, const int* in_sizes, int n_in,
                              void* d_out, int out_size)
{
    const float* x       = (const float*)d_in[0];
    const float* w_dw    = (const float*)d_in[1];
    const float* w_qkv   = (const float*)d_in[2];
    const float* w_qkvdw = (const float*)d_in[3];
    const float* w_proj  = (const float*)d_in[4];
    const float* temp    = (const float*)d_in[5];
    const float* resc    = (const float*)d_in[6];
    float* out = (float*)d_out;

    float *vprep, *vp, *Mp;
    __nv_bfloat16* qkbp;
    cudaGetSymbolAddress((void**)&qkbp,  g_qkb);
    cudaGetSymbolAddress((void**)&vprep, g_vpre);
    cudaGetSymbolAddress((void**)&vp,    g_v);
    cudaGetSymbolAddress((void**)&Mp,    g_M);

    cudaFuncSetAttribute(gemm_mma, cudaFuncAttributePreferredSharedMemoryCarveout, 90);

    k_zero<<<36, 1024>>>();
    k_dw_var<<<BATCH*CDIM, 256>>>(x, w_dw);
    // qkv 1x1 conv: per batch [576,16384] = W[576,192] @ x[b][192,16384]
    // rows <384 -> bf16 (g_qkb), rows >=384 -> fp32 (g_vpre)
    gemm_mma<<<dim3(9, 64, BATCH), 256>>>(w_qkv, x, vprep, qkbp,
        C3, HW, CDIM, 0LL, (long long)CDIM*HW, (long long)CDIM*HW, (long long)384*HW);
    k_dw_qkv<<<BATCH*C3, 256>>>(w_qkvdw);
    k_qk<<<dim3(64, 16), 144>>>();
    k_soft<<<dim3(HEADS, BATCH), 192>>>(temp, resc, w_proj);
    // final: out[b] = M[b](192x192) @ V[b](192x16384)
    gemm_mma<<<dim3(3, 64, BATCH), 256>>>(Mp, vp, out, nullptr,
        CDIM, HW, CDIM, (long long)CDIM*CDIM, (long long)CDIM*HW, (long long)CDIM*HW, 0LL);
}

// round 7
// speedup vs baseline: 2.2119x; 1.1222x over previous
#include <cuda_runtime.h>
#include <cuda_bf16.h>
#include <cstdint>

#define HW   16384
#define CDIM 192
#define C3   576
#define BATCH 8
#define HEADS 8
#define CHD  24

typedef unsigned long long ull;

// ---------------- scratch (device globals: allocation-free rule) ----------------
__device__ __nv_bfloat16 g_xb [25165824];   // [8,192,16384] x in bf16 (for qk gemm)
__device__ __nv_bfloat16 g_wqkb[73728];     // [384,192] W_qkv rows 0..383 in bf16
__device__ __nv_bfloat16 g_qkb[50331648];   // [8,384,16384] pre-conv q,k (bf16)
__device__ float g_vpre[25165824];          // [8,192,16384] pre-conv v (fp32)
__device__ __nv_bfloat16 g_qk[50331648];    // [8,384,16384] post-conv q,k (bf16)
__device__ float g_v  [25165824];           // [8,192,16384] post-conv v (fp32)
__device__ float g_var [BATCH*CDIM];
__device__ float g_norm[BATCH*384];
__device__ float g_S   [BATCH*HEADS*CHD*CHD];
__device__ float g_M   [BATCH*CDIM*CDIM];

__device__ __forceinline__ uint32_t smem_u32(const void* p) {
    uint32_t a;
    asm("{ .reg .u64 t; cvta.to.shared.u64 t, %1; cvt.u32.u64 %0, t; }" : "=r"(a) : "l"(p));
    return a;
}
__device__ __forceinline__ uint32_t f2tf32(float f) {
    uint32_t o;
    asm("cvt.rna.tf32.f32 %0, %1;" : "=r"(o) : "f"(f));
    return o;
}
__device__ __forceinline__ void mma_tf32(float* c, const uint32_t* a, const uint32_t* b) {
    asm volatile(
        "mma.sync.aligned.m16n8k8.row.col.f32.tf32.tf32.f32 "
        "{%0,%1,%2,%3}, {%4,%5,%6,%7}, {%8,%9}, {%0,%1,%2,%3};"
        : "+f"(c[0]), "+f"(c[1]), "+f"(c[2]), "+f"(c[3])
        : "r"(a[0]), "r"(a[1]), "r"(a[2]), "r"(a[3]), "r"(b[0]), "r"(b[1]));
}
__device__ __forceinline__ void mma_bf16(float* c, const uint32_t* a, const uint32_t* b) {
    asm volatile(
        "mma.sync.aligned.m16n8k16.row.col.f32.bf16.bf16.f32 "
        "{%0,%1,%2,%3}, {%4,%5,%6,%7}, {%8,%9}, {%0,%1,%2,%3};"
        : "+f"(c[0]), "+f"(c[1]), "+f"(c[2]), "+f"(c[3])
        : "r"(a[0]), "r"(a[1]), "r"(a[2]), "r"(a[3]), "r"(b[0]), "r"(b[1]));
}
__device__ __forceinline__ void ldsm_x4(uint32_t* r, uint32_t addr) {
    asm volatile("ldmatrix.sync.aligned.m8n8.x4.shared.b16 {%0,%1,%2,%3}, [%4];"
        : "=r"(r[0]), "=r"(r[1]), "=r"(r[2]), "=r"(r[3]) : "r"(addr));
}
__device__ __forceinline__ void ldsm_x4t(uint32_t* r, uint32_t addr) {
    asm volatile("ldmatrix.sync.aligned.m8n8.x4.trans.shared.b16 {%0,%1,%2,%3}, [%4];"
        : "=r"(r[0]), "=r"(r[1]), "=r"(r[2]), "=r"(r[3]) : "r"(addr));
}
__device__ __forceinline__ void cp_async16(uint32_t dst, const void* src) {
    asm volatile("cp.async.cg.shared.global [%0], [%1], 16;" :: "r"(dst), "l"(src) : "memory");
}
__device__ __forceinline__ ull pack2(float a, float b) {
    ull r; asm("mov.b64 %0, {%1,%2};" : "=l"(r) : "f"(a), "f"(b)); return r;
}
__device__ __forceinline__ void ffma2(ull& acc, ull a, ull b) {
    asm("fma.rn.f32x2 %0, %1, %2, %0;" : "+l"(acc) : "l"(a), "l"(b));
}
__device__ __forceinline__ void add2(ull& acc, ull a) {
    asm("add.rn.f32x2 %0, %0, %1;" : "+l"(acc) : "l"(a));
}
__device__ __forceinline__ float2 unpack2(ull v) {
    float2 o; asm("mov.b64 {%0,%1}, %2;" : "=f"(o.x), "=f"(o.y) : "l"(v)); return o;
}

// ================= bf16 mma GEMM for q,k rows: C[384,HW] = A[384,192] @ B[192,HW] =================
// BM=64, BN=256, BK=32, 2-stage cp.async pipeline, 256 threads (8 warps x 64m x 32n slice).
__global__ void __launch_bounds__(256, 2) gemm_bf16(
    const __nv_bfloat16* __restrict__ A,     // [384,192] bf16 (weights, shared over batch)
    const __nv_bfloat16* __restrict__ B,     // [batch][192,HW]
    __nv_bfloat16* __restrict__ C)           // [batch][384,HW]
{
    __shared__ __nv_bfloat16 As[2][64][40];   // stride 80B -> conflict-free ldmatrix
    __shared__ __nv_bfloat16 Bs[2][32][264];  // stride 528B (132w ≡ 4 mod 32)
    const int tid = threadIdx.x, lane = tid & 31, wid = tid >> 5;
    const int g = lane >> 2, t = lane & 3;
    const int bm = blockIdx.x * 64, bn = blockIdx.y * 256;
    const __nv_bfloat16* Bb = B + (size_t)blockIdx.z * CDIM * HW;
    __nv_bfloat16* Cb = C + (size_t)blockIdx.z * 384 * HW;

    const int arow = tid >> 2, akc = (tid & 3) * 8;

    float acc[4][4][4];
    #pragma unroll
    for (int i = 0; i < 4; i++)
        #pragma unroll
        for (int j = 0; j < 4; j++)
            #pragma unroll
            for (int l = 0; l < 4; l++) acc[i][j][l] = 0.f;

    // ldmatrix lane addressing (precompute element indices)
    const int a_m = (lane & 7) + ((lane >> 3) & 1) * 8;    // + ma*16
    const int a_k = ((lane >> 4) & 1) * 8;                 // + kk*16
    const int b_k = (lane & 7) + ((lane >> 3) & 1) * 8;    // + kk*16
    const int b_n = wid * 32 + ((lane >> 4) & 1) * 8;      // + p*16

    // ---- preload stage 0 ----
    cp_async16(smem_u32(&As[0][arow][akc]), &A[(size_t)(bm + arow) * 192 + akc]);
    #pragma unroll
    for (int p = 0; p < 4; p++) {
        int c = tid + p * 256;
        int kr = c >> 5, nc = (c & 31) * 8;
        cp_async16(smem_u32(&Bs[0][kr][nc]), &Bb[(size_t)kr * HW + bn + nc]);
    }
    asm volatile("cp.async.commit_group;" ::: "memory");
    asm volatile("cp.async.wait_group 0;" ::: "memory");
    __syncthreads();

    #pragma unroll 1
    for (int i = 0; i < 6; i++) {
        const int s = i & 1;
        if (i < 5) {
            const int k0 = (i + 1) * 32;
            cp_async16(smem_u32(&As[s ^ 1][arow][akc]), &A[(size_t)(bm + arow) * 192 + k0 + akc]);
            #pragma unroll
            for (int p = 0; p < 4; p++) {
                int c = tid + p * 256;
                int kr = c >> 5, nc = (c & 31) * 8;
                cp_async16(smem_u32(&Bs[s ^ 1][kr][nc]), &Bb[(size_t)(k0 + kr) * HW + bn + nc]);
            }
            asm volatile("cp.async.commit_group;" ::: "memory");
        }
        #pragma unroll
        for (int kk = 0; kk < 2; kk++) {
            uint32_t af[4][4];
            #pragma unroll
            for (int ma = 0; ma < 4; ma++)
                ldsm_x4(af[ma], smem_u32(&As[s][ma * 16 + a_m][kk * 16 + a_k]));
            uint32_t bf[4][4];   // [pair][4 regs] -> frags (p*2, p*2+1)
            #pragma unroll
            for (int p = 0; p < 2; p++)
                ldsm_x4t(bf[p], smem_u32(&Bs[s][kk * 16 + b_k][b_n + p * 16]));
            #pragma unroll
            for (int ma = 0; ma < 4; ma++) {
                #pragma unroll
                for (int p = 0; p < 2; p++) {
                    mma_bf16(acc[ma][p * 2 + 0], af[ma], &bf[p][0]);
                    mma_bf16(acc[ma][p * 2 + 1], af[ma], &bf[p][2]);
                }
            }
        }
        if (i < 5) asm volatile("cp.async.wait_group 0;" ::: "memory");
        __syncthreads();
    }
    // ---- epilogue: bf16 stores ----
    #pragma unroll
    for (int ma = 0; ma < 4; ma++) {
        #pragma unroll
        for (int nt = 0; nt < 4; nt++) {
            const int row = bm + ma * 16 + g;
            const int col = bn + wid * 32 + (nt >> 1) * 16 + (nt & 1) * 8 + 2 * t;
            __nv_bfloat162 h0 = __floats2bfloat162_rn(acc[ma][nt][0], acc[ma][nt][1]);
            __nv_bfloat162 h1 = __floats2bfloat162_rn(acc[ma][nt][2], acc[ma][nt][3]);
            *(__nv_bfloat162*)&Cb[(size_t)row * HW + col]       = h0;
            *(__nv_bfloat162*)&Cb[(size_t)(row + 8) * HW + col] = h1;
        }
    }
}

// ================= tf32 mma.sync batched GEMM (fp32 in/out) =================
__global__ void __launch_bounds__(256, 2) gemm_mma(
    const float* __restrict__ A, const float* __restrict__ B, float* __restrict__ C,
    int M, int N, int K, long long sA, long long sB, long long sC)
{
    __shared__ float As[2][16][72];
    __shared__ float Bs[2][16][264];
    const int tid  = threadIdx.x;
    const int lane = tid & 31;
    const int wid  = tid >> 5;
    const int g    = lane >> 2;
    const int t    = lane & 3;
    const float* Ab = A + (long long)blockIdx.z * sA;
    const float* Bb = B + (long long)blockIdx.z * sB;
    float*       Cb = C + (long long)blockIdx.z * sC;
    const int bm = blockIdx.x * 64;
    const int bn = blockIdx.y * 256;

    const int am    = tid & 63;
    const int ak    = (tid >> 6) << 2;
    const int bnoff = (tid & 63) << 2;
    const int bk    = tid >> 6;

    float acc[4][4][4];
    #pragma unroll
    for (int i = 0; i < 4; i++)
        #pragma unroll
        for (int j = 0; j < 4; j++)
            #pragma unroll
            for (int l = 0; l < 4; l++) acc[i][j][l] = 0.f;

    float4 areg = *(const float4*)&Ab[(size_t)(bm + am) * K + ak];
    #pragma unroll
    for (int p = 0; p < 4; p++)
        cp_async16(smem_u32(&Bs[0][bk + p * 4][bnoff]),
                   &Bb[(size_t)(bk + p * 4) * N + bn + bnoff]);
    asm volatile("cp.async.commit_group;" ::: "memory");
    As[0][ak + 0][am] = __uint_as_float(f2tf32(areg.x));
    As[0][ak + 1][am] = __uint_as_float(f2tf32(areg.y));
    As[0][ak + 2][am] = __uint_as_float(f2tf32(areg.z));
    As[0][ak + 3][am] = __uint_as_float(f2tf32(areg.w));
    asm volatile("cp.async.wait_group 0;" ::: "memory");
    __syncthreads();

    const int nk = K >> 4;
    for (int i = 0; i < nk; i++) {
        const int s = i & 1;
        float4 anext;
        if (i + 1 < nk) {
            const int k0 = (i + 1) << 4;
            anext = *(const float4*)&Ab[(size_t)(bm + am) * K + k0 + ak];
            #pragma unroll
            for (int p = 0; p < 4; p++)
                cp_async16(smem_u32(&Bs[s ^ 1][bk + p * 4][bnoff]),
                           &Bb[(size_t)(k0 + bk + p * 4) * N + bn + bnoff]);
            asm volatile("cp.async.commit_group;" ::: "memory");
        }
        #pragma unroll
        for (int kk = 0; kk < 2; kk++) {
            uint32_t af[4][4];
            #pragma unroll
            for (int ma = 0; ma < 4; ma++) {
                af[ma][0] = __float_as_uint(As[s][kk * 8 + t    ][ma * 16 + g    ]);
                af[ma][1] = __float_as_uint(As[s][kk * 8 + t    ][ma * 16 + g + 8]);
                af[ma][2] = __float_as_uint(As[s][kk * 8 + t + 4][ma * 16 + g    ]);
                af[ma][3] = __float_as_uint(As[s][kk * 8 + t + 4][ma * 16 + g + 8]);
            }
            uint32_t bf[4][2];
            #pragma unroll
            for (int na = 0; na < 4; na++) {
                bf[na][0] = f2tf32(Bs[s][kk * 8 + t    ][wid * 32 + na * 8 + g]);
                bf[na][1] = f2tf32(Bs[s][kk * 8 + t + 4][wid * 32 + na * 8 + g]);
            }
            #pragma unroll
            for (int ma = 0; ma < 4; ma++)
                #pragma unroll
                for (int na = 0; na < 4; na++)
                    mma_tf32(acc[ma][na], af[ma], bf[na]);
        }
        if (i + 1 < nk) {
            As[s ^ 1][ak + 0][am] = __uint_as_float(f2tf32(anext.x));
            As[s ^ 1][ak + 1][am] = __uint_as_float(f2tf32(anext.y));
            As[s ^ 1][ak + 2][am] = __uint_as_float(f2tf32(anext.z));
            As[s ^ 1][ak + 3][am] = __uint_as_float(f2tf32(anext.w));
            asm volatile("cp.async.wait_group 0;" ::: "memory");
        }
        __syncthreads();
    }
    #pragma unroll
    for (int ma = 0; ma < 4; ma++) {
        #pragma unroll
        for (int na = 0; na < 4; na++) {
            const int row = bm + ma * 16 + g;
            const int col = bn + wid * 32 + na * 8 + (t << 1);
            *(float2*)&Cb[(size_t)row * N + col]       = make_float2(acc[ma][na][0], acc[ma][na][1]);
            *(float2*)&Cb[(size_t)(row + 8) * N + col] = make_float2(acc[ma][na][2], acc[ma][na][3]);
        }
    }
}

// ---------------- zero S + convert qk-weights to bf16 ----------------
__global__ void k_zero(const float* __restrict__ w_qkv) {
    int i = blockIdx.x * blockDim.x + threadIdx.x;
    if (i < BATCH*HEADS*CHD*CHD) g_S[i] = 0.f;
    if (i < 384*CDIM) g_wqkb[i] = __float2bfloat16(w_qkv[i]);
}

// =============== rolling-window f32x2 depthwise 3x3 core pieces ===============
__device__ __forceinline__ void conv_loadP(const float* s, int sr, int x4, int lane, ull* P) {
    const float* rp = &s[sr * 132 + x4];
    float4 q = *(const float4*)rp;
    float rx = rp[4];
    float lf = __shfl_up_sync(0xffffffffu, q.w, 1);
    if (lane == 0) lf = 0.f;
    P[0] = pack2(lf,  q.x);
    P[1] = pack2(q.x, q.y);
    P[2] = pack2(q.y, q.z);
    P[3] = pack2(q.z, q.w);
    P[4] = pack2(q.w, rx);
}

#define CONV_ACC(a01, a23, P, o, Wp)                                        \
    {                                                                        \
        _Pragma("unroll")                                                    \
        for (int r = 0; r < 3; r++) {                                        \
            const ull* Q = P[((o) + r) % 3];                                 \
            ffma2(a01, Q[0], Wp[3*r+0]); ffma2(a01, Q[1], Wp[3*r+1]);        \
            ffma2(a01, Q[2], Wp[3*r+2]);                                     \
            ffma2(a23, Q[2], Wp[3*r+0]); ffma2(a23, Q[3], Wp[3*r+1]);        \
            ffma2(a23, Q[4], Wp[3*r+2]);                                     \
        }                                                                    \
    }

// ---------------- depthwise 3x3 on x + variance + x->bf16 emit ----------------
__global__ __launch_bounds__(256) void k_dw_var(const float* __restrict__ x,
                                                const float* __restrict__ wdw)
{
    __shared__ float s[66*132];
    __shared__ float red[64];
    const int bc = blockIdx.x;
    const float* plane = x + (size_t)bc * HW;
    __nv_bfloat16* xbp = g_xb + (size_t)bc * HW;
    const int c = bc % CDIM;
    const int tid = threadIdx.x;
    const int lane = tid & 31;
    const int strip = tid >> 5;
    const int x4 = lane << 2;
    ull Wp[9];
    #pragma unroll
    for (int i = 0; i < 9; i++) { float w = wdw[c*9 + i]; Wp[i] = pack2(w, w); }
    ull accS = 0ull, accQ = 0ull;

    for (int half = 0; half < 2; half++) {
        if (half) __syncthreads();
        const int y0 = half * 64;
        for (int i = tid; i < 66*32; i += 256) {
            int r = i >> 5, j4 = (i & 31) << 2;
            int y = y0 + r - 1;
            float4 v = make_float4(0.f, 0.f, 0.f, 0.f);
            if ((unsigned)y < 128u) v = *(const float4*)&plane[y*128 + j4];
            *(float4*)&s[r*132 + j4] = v;
            if (r >= 1 && r <= 64 && (unsigned)y < 128u) {
                __nv_bfloat162 h0 = __floats2bfloat162_rn(v.x, v.y);
                __nv_bfloat162 h1 = __floats2bfloat162_rn(v.z, v.w);
                uint2 u; u.x = *(uint32_t*)&h0; u.y = *(uint32_t*)&h1;
                *(uint2*)&xbp[y*128 + j4] = u;
            }
        }
        for (int i = tid; i < 66; i += 256) { s[i*132+128] = 0.f; s[i*132+129] = 0.f; }
        __syncthreads();

        ull P[3][5];
        const int base = strip * 8;
        conv_loadP(s, base,     x4, lane, P[0]);
        conv_loadP(s, base + 1, x4, lane, P[1]);
        #pragma unroll
        for (int o = 0; o < 8; o++) {
            conv_loadP(s, base + o + 2, x4, lane, P[(o + 2) % 3]);
            ull a01 = 0ull, a23 = 0ull;
            CONV_ACC(a01, a23, P, o, Wp);
            add2(accS, a01); add2(accS, a23);
            ffma2(accQ, a01, a01); ffma2(accQ, a23, a23);
        }
    }
    float2 S2 = unpack2(accS), Q2 = unpack2(accQ);
    float sum = S2.x + S2.y, sq = Q2.x + Q2.y;
    #pragma unroll
    for (int o = 16; o > 0; o >>= 1) {
        sum += __shfl_down_sync(0xffffffffu, sum, o);
        sq  += __shfl_down_sync(0xffffffffu, sq,  o);
    }
    if (lane == 0) { red[strip] = sum; red[32 + strip] = sq; }
    __syncthreads();
    if (tid == 0) {
        float S = 0.f, Q = 0.f;
        #pragma unroll
        for (int i = 0; i < 8; i++) { S += red[i]; Q += red[32+i]; }
        g_var[bc] = (Q - S*S*(1.f/16384.f)) * (1.f/16383.f);
    }
}

// ---------------- depthwise 3x3 on qkv: q,k bf16->bf16 (+norms), v fp32->fp32 ----------------
__global__ __launch_bounds__(256) void k_dw_qkv(const float* __restrict__ wdw)
{
    __shared__ float s[66*132];
    __shared__ float red[8];
    const int bc = blockIdx.x;                  // b*576 + ch
    const int ch = bc % C3;
    const int b  = bc / C3;
    const bool is_qk = ch < 384;
    const __nv_bfloat16* planeb = g_qkb + ((size_t)b*384 + ch) * HW;
    const float*         planef = g_vpre + ((size_t)b*CDIM + (ch - 384)) * HW;
    __nv_bfloat16* outb = g_qk + ((size_t)b*384 + ch) * HW;
    float*         outv = g_v  + ((size_t)b*CDIM + (ch - 384)) * HW;
    const int tid = threadIdx.x;
    const int lane = tid & 31;
    const int strip = tid >> 5;
    const int x4 = lane << 2;
    ull Wp[9];
    #pragma unroll
    for (int i = 0; i < 9; i++) { float w = wdw[ch*9 + i]; Wp[i] = pack2(w, w); }
    float sq = 0.f;

    for (int half = 0; half < 2; half++) {
        if (half) __syncthreads();
        const int y0 = half * 64;
        if (is_qk) {
            for (int i = tid; i < 66*32; i += 256) {
                int r = i >> 5, j4 = (i & 31) << 2;
                int y = y0 + r - 1;
                float4 v = make_float4(0.f, 0.f, 0.f, 0.f);
                if ((unsigned)y < 128u) {
                    uint2 u = *(const uint2*)&planeb[y*128 + j4];
                    float2 f0 = __bfloat1622float2(*(__nv_bfloat162*)&u.x);
                    float2 f1 = __bfloat1622float2(*(__nv_bfloat162*)&u.y);
                    v = make_float4(f0.x, f0.y, f1.x, f1.y);
                }
                *(float4*)&s[r*132 + j4] = v;
            }
        } else {
            for (int i = tid; i < 66*32; i += 256) {
                int r = i >> 5, j4 = (i & 31) << 2;
                int y = y0 + r - 1;
                float4 v = make_float4(0.f, 0.f, 0.f, 0.f);
                if ((unsigned)y < 128u) v = *(const float4*)&planef[y*128 + j4];
                *(float4*)&s[r*132 + j4] = v;
            }
        }
        for (int i = tid; i < 66; i += 256) { s[i*132+128] = 0.f; s[i*132+129] = 0.f; }
        __syncthreads();

        ull P[3][5];
        const int base = strip * 8;
        conv_loadP(s, base,     x4, lane, P[0]);
        conv_loadP(s, base + 1, x4, lane, P[1]);
        #pragma unroll
        for (int o = 0; o < 8; o++) {
            conv_loadP(s, base + o + 2, x4, lane, P[(o + 2) % 3]);
            ull a01 = 0ull, a23 = 0ull;
            CONV_ACC(a01, a23, P, o, Wp);
            const int y = y0 + base + o;
            float2 v01 = unpack2(a01), v23 = unpack2(a23);
            if (is_qk) {
                __nv_bfloat162 h0 = __floats2bfloat162_rn(v01.x, v01.y);
                __nv_bfloat162 h1 = __floats2bfloat162_rn(v23.x, v23.y);
                uint2 st;
                st.x = *(uint32_t*)&h0; st.y = *(uint32_t*)&h1;
                *(uint2*)&outb[y*128 + x4] = st;
                float2 r0 = __bfloat1622float2(h0), r1 = __bfloat1622float2(h1);
                sq += r0.x*r0.x + r0.y*r0.y + r1.x*r1.x + r1.y*r1.y;
            } else {
                *(float4*)&outv[y*128 + x4] = make_float4(v01.x, v01.y, v23.x, v23.y);
            }
        }
    }
    if (is_qk) {
        #pragma unroll
        for (int o = 16; o > 0; o >>= 1) sq += __shfl_down_sync(0xffffffffu, sq, o);
        if (lane == 0) red[strip] = sq;
        __syncthreads();
        if (tid == 0) {
            float Q = 0.f;
            #pragma unroll
            for (int i = 0; i < 8; i++) Q += red[i];
            g_norm[b*384 + ch] = Q;
        }
    }
}

// ---------------- S = q @ k^T per (b,h) from bf16, split-K with atomics ----------------
__global__ __launch_bounds__(144) void k_qk()
{
    __shared__ float qs[24][64];
    __shared__ float ks[24][64];
    const int bh = blockIdx.x;
    const int b = bh >> 3, h = bh & 7;
    const __nv_bfloat16* qb = g_qk + ((size_t)b*384 + h*CHD) * HW;
    const __nv_bfloat16* kb = g_qk + ((size_t)b*384 + 192 + h*CHD) * HW;
    const int n0 = blockIdx.y * 1024;
    const int tid = threadIdx.x;
    const int sub = tid & 3;
    const int cd  = tid >> 2;
    const int c0 = (cd / 6) * 4, d0 = (cd % 6) * 4;
    float acc[4][4] = {};
    for (int chk = 0; chk < 16; chk++) {
        if (chk) __syncthreads();
        const int nn = n0 + chk * 64;
        for (int i = tid; i < 24*32; i += 144) {
            int r = i >> 5, j2 = (i & 31) << 1;
            __nv_bfloat162 q2 = *(const __nv_bfloat162*)&qb[(size_t)r*HW + nn + j2];
            __nv_bfloat162 k2 = *(const __nv_bfloat162*)&kb[(size_t)r*HW + nn + j2];
            *(float2*)&qs[r][j2] = __bfloat1622float2(q2);
            *(float2*)&ks[r][j2] = __bfloat1622float2(k2);
        }
        __syncthreads();
        const int j0 = sub * 16;
        #pragma unroll 4
        for (int j = j0; j < j0 + 16; j++) {
            float q0 = qs[c0+0][j], q1 = qs[c0+1][j], q2 = qs[c0+2][j], q3 = qs[c0+3][j];
            float k0 = ks[d0+0][j], k1 = ks[d0+1][j], k2 = ks[d0+2][j], k3 = ks[d0+3][j];
            acc[0][0] += q0*k0; acc[0][1] += q0*k1; acc[0][2] += q0*k2; acc[0][3] += q0*k3;
            acc[1][0] += q1*k0; acc[1][1] += q1*k1; acc[1][2] += q1*k2; acc[1][3] += q1*k3;
            acc[2][0] += q2*k0; acc[2][1] += q2*k1; acc[2][2] += q2*k2; acc[2][3] += q2*k3;
            acc[3][0] += q3*k0; acc[3][1] += q3*k1; acc[3][2] += q3*k2; acc[3][3] += q3*k3;
        }
    }
    #pragma unroll
    for (int i = 0; i < 4; i++)
        #pragma unroll
        for (int l = 0; l < 4; l++)
            atomicAdd(&g_S[(size_t)bh*576 + (c0+i)*24 + (d0+l)], acc[i][l]);
}

// ---------------- softmax + M = Wproj @ blockdiag(attn) ----------------
__global__ __launch_bounds__(192) void k_soft(const float* __restrict__ temp,
                                              const float* __restrict__ resc,
                                              const float* __restrict__ wproj)
{
    __shared__ float a[24][24];
    const int h = blockIdx.x, b = blockIdx.y;
    const int tid = threadIdx.x;
    const float* Sp = g_S + (size_t)(b*8 + h) * 576;
    const float t = temp[h];
    for (int idx = tid; idx < 576; idx += 192) {
        int c = idx / 24, d = idx % 24;
        float nq = sqrtf(g_norm[b*384 + h*24 + c]);
        float nk = sqrtf(g_norm[b*384 + 192 + h*24 + d]);
        float denom = fmaxf(nq, 1e-12f) * fmaxf(nk, 1e-12f);
        float l = Sp[idx] / denom * t;
        if (c == d) l += resc[h] * g_var[b*192 + h*24 + c];
        a[c][d] = l;
    }
    __syncthreads();
    if (tid < 24) {
        const int c = tid;
        float m = -1e30f;
        #pragma unroll
        for (int d = 0; d < 24; d++) m = fmaxf(m, a[c][d]);
        float e[24]; float ssum = 0.f;
        #pragma unroll
        for (int d = 0; d < 24; d++) { e[d] = expf(a[c][d] - m); ssum += e[d]; }
        float inv = 1.f / ssum;
        #pragma unroll
        for (int d = 0; d < 24; d++) a[c][d] = e[d] * inv;
    }
    __syncthreads();
    const int co = tid;
    float wr[24];
    #pragma unroll
    for (int c = 0; c < 24; c++) wr[c] = wproj[(size_t)co*CDIM + h*24 + c];
    float* Mp = g_M + (size_t)b*CDIM*CDIM + (size_t)co*CDIM + h*24;
    #pragma unroll 4
    for (int d = 0; d < 24; d++) {
        float accv = 0.f;
        #pragma unroll
        for (int c = 0; c < 24; c++) accv += wr[c] * a[c][d];
        Mp[d] = accv;
    }
}

// ---------------- launch ----------------
extern "C" void kernel_launch(void* const* d_in, const int* in_sizes, int n_in,
                              void* d_out, int out_size)
{
    const float* x       = (const float*)d_in[0];
    const float* w_dw    = (const float*)d_in[1];
    const float* w_qkv   = (const float*)d_in[2];
    const float* w_qkvdw = (const float*)d_in[3];
    const float* w_proj  = (const float*)d_in[4];
    const float* temp    = (const float*)d_in[5];
    const float* resc    = (const float*)d_in[6];
    float* out = (float*)d_out;

    float *vprep, *vp, *Mp;
    __nv_bfloat16 *qkbp, *xbp, *wqkbp;
    cudaGetSymbolAddress((void**)&qkbp,  g_qkb);
    cudaGetSymbolAddress((void**)&xbp,   g_xb);
    cudaGetSymbolAddress((void**)&wqkbp, g_wqkb);
    cudaGetSymbolAddress((void**)&vprep, g_vpre);
    cudaGetSymbolAddress((void**)&vp,    g_v);
    cudaGetSymbolAddress((void**)&Mp,    g_M);

    cudaFuncSetAttribute(gemm_mma,  cudaFuncAttributePreferredSharedMemoryCarveout, 90);
    cudaFuncSetAttribute(gemm_bf16, cudaFuncAttributePreferredSharedMemoryCarveout, 90);

    k_zero<<<72, 1024>>>(w_qkv);
    k_dw_var<<<BATCH*CDIM, 256>>>(x, w_dw);     // also emits g_xb (bf16 x)
    // q,k rows of 1x1 conv (bf16 tensor path): [384,HW] = Wqk[384,192] @ xb[192,HW]
    gemm_bf16<<<dim3(6, 64, BATCH), 256>>>(wqkbp, xbp, qkbp);
    // v rows (fp32/tf32 path): [192,HW] = Wv[192,192] @ x[192,HW]
    gemm_mma<<<dim3(3, 64, BATCH), 256>>>(w_qkv + (size_t)384*CDIM, x, vprep,
        CDIM, HW, CDIM, 0LL, (long long)CDIM*HW, (long long)CDIM*HW);
    k_dw_qkv<<<BATCH*C3, 256>>>(w_qkvdw);
    k_qk<<<dim3(64, 16), 144>>>();
    k_soft<<<dim3(HEADS, BATCH), 192>>>(temp, resc, w_proj);
    // final: out[b] = M[b](192x192) @ V[b](192,HW)
    gemm_mma<<<dim3(3, 64, BATCH), 256>>>(Mp, vp, out,
        CDIM, HW, CDIM, (long long)CDIM*CDIM, (long long)CDIM*HW, (long long)CDIM*HW);
}

// round 8
// speedup vs baseline: 2.3400x; 1.0579x over previous
#include <cuda_runtime.h>
#include <cuda_bf16.h>
#include <cstdint>

#define HW   16384
#define CDIM 192
#define C3   576
#define BATCH 8
#define HEADS 8
#define CHD  24

typedef unsigned long long ull;

// ---------------- scratch (device globals: allocation-free rule) ----------------
__device__ __nv_bfloat16 g_xb [25165824];   // [8,192,16384] x in bf16 (for qk gemm)
__device__ __nv_bfloat16 g_wqkb[73728];     // [384,192] W_qkv rows 0..383 in bf16
__device__ __nv_bfloat16 g_qkb[50331648];   // [8,384,16384] pre-conv q,k (bf16)
__device__ float g_vpre[25165824];          // [8,192,16384] pre-conv v (fp32)
__device__ __nv_bfloat16 g_qk[50331648];    // [8,384,16384] post-conv q,k (bf16)
__device__ float g_v  [25165824];           // [8,192,16384] post-conv v (fp32)
__device__ float g_var [BATCH*CDIM];
__device__ float g_norm[BATCH*384];
__device__ float g_S   [BATCH*HEADS*CHD*CHD];
__device__ float g_M   [BATCH*CDIM*CDIM];

__device__ __forceinline__ uint32_t smem_u32(const void* p) {
    uint32_t a;
    asm("{ .reg .u64 t; cvta.to.shared.u64 t, %1; cvt.u32.u64 %0, t; }" : "=r"(a) : "l"(p));
    return a;
}
__device__ __forceinline__ uint32_t f2tf32(float f) {
    uint32_t o;
    asm("cvt.rna.tf32.f32 %0, %1;" : "=r"(o) : "f"(f));
    return o;
}
__device__ __forceinline__ void mma_tf32(float* c, const uint32_t* a, const uint32_t* b) {
    asm volatile(
        "mma.sync.aligned.m16n8k8.row.col.f32.tf32.tf32.f32 "
        "{%0,%1,%2,%3}, {%4,%5,%6,%7}, {%8,%9}, {%0,%1,%2,%3};"
        : "+f"(c[0]), "+f"(c[1]), "+f"(c[2]), "+f"(c[3])
        : "r"(a[0]), "r"(a[1]), "r"(a[2]), "r"(a[3]), "r"(b[0]), "r"(b[1]));
}
__device__ __forceinline__ void mma_bf16(float* c, const uint32_t* a, const uint32_t* b) {
    asm volatile(
        "mma.sync.aligned.m16n8k16.row.col.f32.bf16.bf16.f32 "
        "{%0,%1,%2,%3}, {%4,%5,%6,%7}, {%8,%9}, {%0,%1,%2,%3};"
        : "+f"(c[0]), "+f"(c[1]), "+f"(c[2]), "+f"(c[3])
        : "r"(a[0]), "r"(a[1]), "r"(a[2]), "r"(a[3]), "r"(b[0]), "r"(b[1]));
}
__device__ __forceinline__ void ldsm_x4(uint32_t* r, uint32_t addr) {
    asm volatile("ldmatrix.sync.aligned.m8n8.x4.shared.b16 {%0,%1,%2,%3}, [%4];"
        : "=r"(r[0]), "=r"(r[1]), "=r"(r[2]), "=r"(r[3]) : "r"(addr));
}
__device__ __forceinline__ void ldsm_x4t(uint32_t* r, uint32_t addr) {
    asm volatile("ldmatrix.sync.aligned.m8n8.x4.trans.shared.b16 {%0,%1,%2,%3}, [%4];"
        : "=r"(r[0]), "=r"(r[1]), "=r"(r[2]), "=r"(r[3]) : "r"(addr));
}
__device__ __forceinline__ void cp_async16(uint32_t dst, const void* src) {
    asm volatile("cp.async.cg.shared.global [%0], [%1], 16;" :: "r"(dst), "l"(src) : "memory");
}
__device__ __forceinline__ ull pack2(float a, float b) {
    ull r; asm("mov.b64 %0, {%1,%2};" : "=l"(r) : "f"(a), "f"(b)); return r;
}
__device__ __forceinline__ void ffma2(ull& acc, ull a, ull b) {
    asm("fma.rn.f32x2 %0, %1, %2, %0;" : "+l"(acc) : "l"(a), "l"(b));
}
__device__ __forceinline__ void add2(ull& acc, ull a) {
    asm("add.rn.f32x2 %0, %0, %1;" : "+l"(acc) : "l"(a));
}
__device__ __forceinline__ float2 unpack2(ull v) {
    float2 o; asm("mov.b64 {%0,%1}, %2;" : "=f"(o.x), "=f"(o.y) : "l"(v)); return o;
}

// ================= bf16 mma GEMM for q,k rows: C[384,HW] = A[384,192] @ B[192,HW] =================
__global__ void __launch_bounds__(256, 2) gemm_bf16(
    const __nv_bfloat16* __restrict__ A,
    const __nv_bfloat16* __restrict__ B,
    __nv_bfloat16* __restrict__ C)
{
    __shared__ __nv_bfloat16 As[2][64][40];
    __shared__ __nv_bfloat16 Bs[2][32][264];
    const int tid = threadIdx.x, lane = tid & 31, wid = tid >> 5;
    const int g = lane >> 2, t = lane & 3;
    const int bm = blockIdx.x * 64, bn = blockIdx.y * 256;
    const __nv_bfloat16* Bb = B + (size_t)blockIdx.z * CDIM * HW;
    __nv_bfloat16* Cb = C + (size_t)blockIdx.z * 384 * HW;

    const int arow = tid >> 2, akc = (tid & 3) * 8;

    float acc[4][4][4];
    #pragma unroll
    for (int i = 0; i < 4; i++)
        #pragma unroll
        for (int j = 0; j < 4; j++)
            #pragma unroll
            for (int l = 0; l < 4; l++) acc[i][j][l] = 0.f;

    const int a_m = (lane & 15);
    const int a_k = ((lane >> 4) & 1) * 8;
    const int b_k = (lane & 7) + ((lane >> 3) & 1) * 8;
    const int b_n = wid * 32 + ((lane >> 4) & 1) * 8;

    cp_async16(smem_u32(&As[0][arow][akc]), &A[(size_t)(bm + arow) * 192 + akc]);
    #pragma unroll
    for (int p = 0; p < 4; p++) {
        int c = tid + p * 256;
        int kr = c >> 5, nc = (c & 31) * 8;
        cp_async16(smem_u32(&Bs[0][kr][nc]), &Bb[(size_t)kr * HW + bn + nc]);
    }
    asm volatile("cp.async.commit_group;" ::: "memory");
    asm volatile("cp.async.wait_group 0;" ::: "memory");
    __syncthreads();

    #pragma unroll 1
    for (int i = 0; i < 6; i++) {
        const int s = i & 1;
        if (i < 5) {
            const int k0 = (i + 1) * 32;
            cp_async16(smem_u32(&As[s ^ 1][arow][akc]), &A[(size_t)(bm + arow) * 192 + k0 + akc]);
            #pragma unroll
            for (int p = 0; p < 4; p++) {
                int c = tid + p * 256;
                int kr = c >> 5, nc = (c & 31) * 8;
                cp_async16(smem_u32(&Bs[s ^ 1][kr][nc]), &Bb[(size_t)(k0 + kr) * HW + bn + nc]);
            }
            asm volatile("cp.async.commit_group;" ::: "memory");
        }
        #pragma unroll
        for (int kk = 0; kk < 2; kk++) {
            uint32_t af[4][4];
            #pragma unroll
            for (int ma = 0; ma < 4; ma++)
                ldsm_x4(af[ma], smem_u32(&As[s][ma * 16 + a_m][kk * 16 + a_k]));
            uint32_t bf[4][4];
            #pragma unroll
            for (int p = 0; p < 2; p++)
                ldsm_x4t(bf[p], smem_u32(&Bs[s][kk * 16 + b_k][b_n + p * 16]));
            #pragma unroll
            for (int ma = 0; ma < 4; ma++) {
                #pragma unroll
                for (int p = 0; p < 2; p++) {
                    mma_bf16(acc[ma][p * 2 + 0], af[ma], &bf[p][0]);
                    mma_bf16(acc[ma][p * 2 + 1], af[ma], &bf[p][2]);
                }
            }
        }
        if (i < 5) asm volatile("cp.async.wait_group 0;" ::: "memory");
        __syncthreads();
    }
    #pragma unroll
    for (int ma = 0; ma < 4; ma++) {
        #pragma unroll
        for (int nt = 0; nt < 4; nt++) {
            const int row = bm + ma * 16 + g;
            const int col = bn + wid * 32 + (nt >> 1) * 16 + (nt & 1) * 8 + 2 * t;
            __nv_bfloat162 h0 = __floats2bfloat162_rn(acc[ma][nt][0], acc[ma][nt][1]);
            __nv_bfloat162 h1 = __floats2bfloat162_rn(acc[ma][nt][2], acc[ma][nt][3]);
            *(__nv_bfloat162*)&Cb[(size_t)row * HW + col]       = h0;
            *(__nv_bfloat162*)&Cb[(size_t)(row + 8) * HW + col] = h1;
        }
    }
}

// ================= tf32 mma.sync GEMM, ldmatrix-b32 A frags, BK=32 =================
// C[M,N] = A[M,K] @ B[K,N], fp32 in/out. BM=64, BN=256, BK=32, 256 threads.
// As k-major [m][36] (stride 36 floats -> ldmatrix rows hit banks 4i, conflict-free).
__global__ void __launch_bounds__(256, 2) gemm_mma(
    const float* __restrict__ A, const float* __restrict__ B, float* __restrict__ C,
    int M, int N, int K, long long sA, long long sB, long long sC)
{
    __shared__ float As[2][64][36];
    __shared__ float Bs[2][32][264];
    const int tid  = threadIdx.x;
    const int lane = tid & 31;
    const int wid  = tid >> 5;
    const int g    = lane >> 2;
    const int t    = lane & 3;
    const float* Ab = A + (long long)blockIdx.z * sA;
    const float* Bb = B + (long long)blockIdx.z * sB;
    float*       Cb = C + (long long)blockIdx.z * sC;
    const int bm = blockIdx.x * 64;
    const int bn = blockIdx.y * 256;

    const int arow = tid >> 2;            // 0..63
    const int acol = (tid & 3) * 8;       // 0,8,16,24
    // ldmatrix lane addressing for A frags: row = ma*16 + (lane&15), kcol = kk*8 + (lane>>4)*4
    const int a_m = lane & 15;
    const int a_k = (lane >> 4) * 4;

    float acc[4][4][4];
    #pragma unroll
    for (int i = 0; i < 4; i++)
        #pragma unroll
        for (int j = 0; j < 4; j++)
            #pragma unroll
            for (int l = 0; l < 4; l++) acc[i][j][l] = 0.f;

    // ---- preload stage 0 ----
    {
        const float* ap = &Ab[(size_t)(bm + arow) * K + acol];
        float4 a0 = *(const float4*)ap, a1 = *(const float4*)(ap + 4);
        float4 c0, c1;
        c0.x = __uint_as_float(f2tf32(a0.x)); c0.y = __uint_as_float(f2tf32(a0.y));
        c0.z = __uint_as_float(f2tf32(a0.z)); c0.w = __uint_as_float(f2tf32(a0.w));
        c1.x = __uint_as_float(f2tf32(a1.x)); c1.y = __uint_as_float(f2tf32(a1.y));
        c1.z = __uint_as_float(f2tf32(a1.z)); c1.w = __uint_as_float(f2tf32(a1.w));
        *(float4*)&As[0][arow][acol]     = c0;
        *(float4*)&As[0][arow][acol + 4] = c1;
    }
    #pragma unroll
    for (int p = 0; p < 8; p++) {
        int c = tid + p * 256;
        int kr = c >> 6, nc = (c & 63) * 4;
        cp_async16(smem_u32(&Bs[0][kr][nc]), &Bb[(size_t)kr * N + bn + nc]);
    }
    asm volatile("cp.async.commit_group;" ::: "memory");
    asm volatile("cp.async.wait_group 0;" ::: "memory");
    __syncthreads();

    const int nchunk = K >> 5;    // 6 for K=192
    #pragma unroll 1
    for (int i = 0; i < nchunk; i++) {
        const int s = i & 1;
        if (i + 1 < nchunk) {
            const int k0 = (i + 1) << 5;
            // A prefetch: LDG -> cvt -> STS into s^1 (consumed stage, safe after last sync)
            const float* ap = &Ab[(size_t)(bm + arow) * K + k0 + acol];
            float4 a0 = *(const float4*)ap, a1 = *(const float4*)(ap + 4);
            float4 c0, c1;
            c0.x = __uint_as_float(f2tf32(a0.x)); c0.y = __uint_as_float(f2tf32(a0.y));
            c0.z = __uint_as_float(f2tf32(a0.z)); c0.w = __uint_as_float(f2tf32(a0.w));
            c1.x = __uint_as_float(f2tf32(a1.x)); c1.y = __uint_as_float(f2tf32(a1.y));
            c1.z = __uint_as_float(f2tf32(a1.z)); c1.w = __uint_as_float(f2tf32(a1.w));
            *(float4*)&As[s ^ 1][arow][acol]     = c0;
            *(float4*)&As[s ^ 1][arow][acol + 4] = c1;
            #pragma unroll
            for (int p = 0; p < 8; p++) {
                int c = tid + p * 256;
                int kr = c >> 6, nc = (c & 63) * 4;
                cp_async16(smem_u32(&Bs[s ^ 1][kr][nc]), &Bb[(size_t)(k0 + kr) * N + bn + nc]);
            }
            asm volatile("cp.async.commit_group;" ::: "memory");
        }
        #pragma unroll
        for (int kk = 0; kk < 4; kk++) {
            uint32_t af[4][4];
            #pragma unroll
            for (int ma = 0; ma < 4; ma++)
                ldsm_x4(af[ma], smem_u32(&As[s][ma * 16 + a_m][kk * 8 + a_k]));
            uint32_t bf[4][2];
            #pragma unroll
            for (int na = 0; na < 4; na++) {
                bf[na][0] = f2tf32(Bs[s][kk * 8 + t    ][wid * 32 + na * 8 + g]);
                bf[na][1] = f2tf32(Bs[s][kk * 8 + t + 4][wid * 32 + na * 8 + g]);
            }
            #pragma unroll
            for (int ma = 0; ma < 4; ma++)
                #pragma unroll
                for (int na = 0; na < 4; na++)
                    mma_tf32(acc[ma][na], af[ma], bf[na]);
        }
        if (i + 1 < nchunk) asm volatile("cp.async.wait_group 0;" ::: "memory");
        __syncthreads();
    }
    #pragma unroll
    for (int ma = 0; ma < 4; ma++) {
        #pragma unroll
        for (int na = 0; na < 4; na++) {
            const int row = bm + ma * 16 + g;
            const int col = bn + wid * 32 + na * 8 + (t << 1);
            *(float2*)&Cb[(size_t)row * N + col]       = make_float2(acc[ma][na][0], acc[ma][na][1]);
            *(float2*)&Cb[(size_t)(row + 8) * N + col] = make_float2(acc[ma][na][2], acc[ma][na][3]);
        }
    }
}

// ---------------- zero S + convert qk-weights to bf16 ----------------
__global__ void k_zero(const float* __restrict__ w_qkv) {
    int i = blockIdx.x * blockDim.x + threadIdx.x;
    if (i < BATCH*HEADS*CHD*CHD) g_S[i] = 0.f;
    if (i < 384*CDIM) g_wqkb[i] = __float2bfloat16(w_qkv[i]);
}

// =============== rolling-window f32x2 depthwise 3x3 core pieces ===============
__device__ __forceinline__ void conv_loadP(const float* s, int sr, int x4, int lane, ull* P) {
    const float* rp = &s[sr * 132 + x4];
    float4 q = *(const float4*)rp;
    float rx = rp[4];
    float lf = __shfl_up_sync(0xffffffffu, q.w, 1);
    if (lane == 0) lf = 0.f;
    P[0] = pack2(lf,  q.x);
    P[1] = pack2(q.x, q.y);
    P[2] = pack2(q.y, q.z);
    P[3] = pack2(q.z, q.w);
    P[4] = pack2(q.w, rx);
}

#define CONV_ACC(a01, a23, P, o, Wp)                                        \
    {                                                                        \
        _Pragma("unroll")                                                    \
        for (int r = 0; r < 3; r++) {                                        \
            const ull* Q = P[((o) + r) % 3];                                 \
            ffma2(a01, Q[0], Wp[3*r+0]); ffma2(a01, Q[1], Wp[3*r+1]);        \
            ffma2(a01, Q[2], Wp[3*r+2]);                                     \
            ffma2(a23, Q[2], Wp[3*r+0]); ffma2(a23, Q[3], Wp[3*r+1]);        \
            ffma2(a23, Q[4], Wp[3*r+2]);                                     \
        }                                                                    \
    }

// ---------------- depthwise 3x3 on x + variance + x->bf16 emit ----------------
__global__ __launch_bounds__(256) void k_dw_var(const float* __restrict__ x,
                                                const float* __restrict__ wdw)
{
    __shared__ float s[66*132];
    __shared__ float red[64];
    const int bc = blockIdx.x;
    const float* plane = x + (size_t)bc * HW;
    __nv_bfloat16* xbp = g_xb + (size_t)bc * HW;
    const int c = bc % CDIM;
    const int tid = threadIdx.x;
    const int lane = tid & 31;
    const int strip = tid >> 5;
    const int x4 = lane << 2;
    ull Wp[9];
    #pragma unroll
    for (int i = 0; i < 9; i++) { float w = wdw[c*9 + i]; Wp[i] = pack2(w, w); }
    ull accS = 0ull, accQ = 0ull;

    for (int half = 0; half < 2; half++) {
        if (half) __syncthreads();
        const int y0 = half * 64;
        for (int i = tid; i < 66*32; i += 256) {
            int r = i >> 5, j4 = (i & 31) << 2;
            int y = y0 + r - 1;
            float4 v = make_float4(0.f, 0.f, 0.f, 0.f);
            if ((unsigned)y < 128u) v = *(const float4*)&plane[y*128 + j4];
            *(float4*)&s[r*132 + j4] = v;
            if (r >= 1 && r <= 64 && (unsigned)y < 128u) {
                __nv_bfloat162 h0 = __floats2bfloat162_rn(v.x, v.y);
                __nv_bfloat162 h1 = __floats2bfloat162_rn(v.z, v.w);
                uint2 u; u.x = *(uint32_t*)&h0; u.y = *(uint32_t*)&h1;
                *(uint2*)&xbp[y*128 + j4] = u;
            }
        }
        for (int i = tid; i < 66; i += 256) { s[i*132+128] = 0.f; s[i*132+129] = 0.f; }
        __syncthreads();

        ull P[3][5];
        const int base = strip * 8;
        conv_loadP(s, base,     x4, lane, P[0]);
        conv_loadP(s, base + 1, x4, lane, P[1]);
        #pragma unroll
        for (int o = 0; o < 8; o++) {
            conv_loadP(s, base + o + 2, x4, lane, P[(o + 2) % 3]);
            ull a01 = 0ull, a23 = 0ull;
            CONV_ACC(a01, a23, P, o, Wp);
            add2(accS, a01); add2(accS, a23);
            ffma2(accQ, a01, a01); ffma2(accQ, a23, a23);
        }
    }
    float2 S2 = unpack2(accS), Q2 = unpack2(accQ);
    float sum = S2.x + S2.y, sq = Q2.x + Q2.y;
    #pragma unroll
    for (int o = 16; o > 0; o >>= 1) {
        sum += __shfl_down_sync(0xffffffffu, sum, o);
        sq  += __shfl_down_sync(0xffffffffu, sq,  o);
    }
    if (lane == 0) { red[strip] = sum; red[32 + strip] = sq; }
    __syncthreads();
    if (tid == 0) {
        float S = 0.f, Q = 0.f;
        #pragma unroll
        for (int i = 0; i < 8; i++) { S += red[i]; Q += red[32+i]; }
        g_var[bc] = (Q - S*S*(1.f/16384.f)) * (1.f/16383.f);
    }
}

// ---------------- depthwise 3x3 on qkv: q,k bf16->bf16 (+norms), v fp32->fp32 ----------------
__global__ __launch_bounds__(256) void k_dw_qkv(const float* __restrict__ wdw)
{
    __shared__ float s[66*132];
    __shared__ float red[8];
    const int bc = blockIdx.x;
    const int ch = bc % C3;
    const int b  = bc / C3;
    const bool is_qk = ch < 384;
    const __nv_bfloat16* planeb = g_qkb + ((size_t)b*384 + ch) * HW;
    const float*         planef = g_vpre + ((size_t)b*CDIM + (ch - 384)) * HW;
    __nv_bfloat16* outb = g_qk + ((size_t)b*384 + ch) * HW;
    float*         outv = g_v  + ((size_t)b*CDIM + (ch - 384)) * HW;
    const int tid = threadIdx.x;
    const int lane = tid & 31;
    const int strip = tid >> 5;
    const int x4 = lane << 2;
    ull Wp[9];
    #pragma unroll
    for (int i = 0; i < 9; i++) { float w = wdw[ch*9 + i]; Wp[i] = pack2(w, w); }
    float sq = 0.f;

    for (int half = 0; half < 2; half++) {
        if (half) __syncthreads();
        const int y0 = half * 64;
        if (is_qk) {
            for (int i = tid; i < 66*32; i += 256) {
                int r = i >> 5, j4 = (i & 31) << 2;
                int y = y0 + r - 1;
                float4 v = make_float4(0.f, 0.f, 0.f, 0.f);
                if ((unsigned)y < 128u) {
                    uint2 u = *(const uint2*)&planeb[y*128 + j4];
                    float2 f0 = __bfloat1622float2(*(__nv_bfloat162*)&u.x);
                    float2 f1 = __bfloat1622float2(*(__nv_bfloat162*)&u.y);
                    v = make_float4(f0.x, f0.y, f1.x, f1.y);
                }
                *(float4*)&s[r*132 + j4] = v;
            }
        } else {
            for (int i = tid; i < 66*32; i += 256) {
                int r = i >> 5, j4 = (i & 31) << 2;
                int y = y0 + r - 1;
                float4 v = make_float4(0.f, 0.f, 0.f, 0.f);
                if ((unsigned)y < 128u) v = *(const float4*)&planef[y*128 + j4];
                *(float4*)&s[r*132 + j4] = v;
            }
        }
        for (int i = tid; i < 66; i += 256) { s[i*132+128] = 0.f; s[i*132+129] = 0.f; }
        __syncthreads();

        ull P[3][5];
        const int base = strip * 8;
        conv_loadP(s, base,     x4, lane, P[0]);
        conv_loadP(s, base + 1, x4, lane, P[1]);
        #pragma unroll
        for (int o = 0; o < 8; o++) {
            conv_loadP(s, base + o + 2, x4, lane, P[(o + 2) % 3]);
            ull a01 = 0ull, a23 = 0ull;
            CONV_ACC(a01, a23, P, o, Wp);
            const int y = y0 + base + o;
            float2 v01 = unpack2(a01), v23 = unpack2(a23);
            if (is_qk) {
                __nv_bfloat162 h0 = __floats2bfloat162_rn(v01.x, v01.y);
                __nv_bfloat162 h1 = __floats2bfloat162_rn(v23.x, v23.y);
                uint2 st;
                st.x = *(uint32_t*)&h0; st.y = *(uint32_t*)&h1;
                *(uint2*)&outb[y*128 + x4] = st;
                float2 r0 = __bfloat1622float2(h0), r1 = __bfloat1622float2(h1);
                sq += r0.x*r0.x + r0.y*r0.y + r1.x*r1.x + r1.y*r1.y;
            } else {
                *(float4*)&outv[y*128 + x4] = make_float4(v01.x, v01.y, v23.x, v23.y);
            }
        }
    }
    if (is_qk) {
        #pragma unroll
        for (int o = 16; o > 0; o >>= 1) sq += __shfl_down_sync(0xffffffffu, sq, o);
        if (lane == 0) red[strip] = sq;
        __syncthreads();
        if (tid == 0) {
            float Q = 0.f;
            #pragma unroll
            for (int i = 0; i < 8; i++) Q += red[i];
            g_norm[b*384 + ch] = Q;
        }
    }
}

// ---------------- S = q @ k^T per (b,h) from bf16, split-K with atomics ----------------
__global__ __launch_bounds__(144) void k_qk()
{
    __shared__ float qs[24][64];
    __shared__ float ks[24][64];
    const int bh = blockIdx.x;
    const int b = bh >> 3, h = bh & 7;
    const __nv_bfloat16* qb = g_qk + ((size_t)b*384 + h*CHD) * HW;
    const __nv_bfloat16* kb = g_qk + ((size_t)b*384 + 192 + h*CHD) * HW;
    const int n0 = blockIdx.y * 1024;
    const int tid = threadIdx.x;
    const int sub = tid & 3;
    const int cd  = tid >> 2;
    const int c0 = (cd / 6) * 4, d0 = (cd % 6) * 4;
    float acc[4][4] = {};
    for (int chk = 0; chk < 16; chk++) {
        if (chk) __syncthreads();
        const int nn = n0 + chk * 64;
        for (int i = tid; i < 24*32; i += 144) {
            int r = i >> 5, j2 = (i & 31) << 1;
            __nv_bfloat162 q2 = *(const __nv_bfloat162*)&qb[(size_t)r*HW + nn + j2];
            __nv_bfloat162 k2 = *(const __nv_bfloat162*)&kb[(size_t)r*HW + nn + j2];
            *(float2*)&qs[r][j2] = __bfloat1622float2(q2);
            *(float2*)&ks[r][j2] = __bfloat1622float2(k2);
        }
        __syncthreads();
        const int j0 = sub * 16;
        #pragma unroll 4
        for (int j = j0; j < j0 + 16; j++) {
            float q0 = qs[c0+0][j], q1 = qs[c0+1][j], q2 = qs[c0+2][j], q3 = qs[c0+3][j];
            float k0 = ks[d0+0][j], k1 = ks[d0+1][j], k2 = ks[d0+2][j], k3 = ks[d0+3][j];
            acc[0][0] += q0*k0; acc[0][1] += q0*k1; acc[0][2] += q0*k2; acc[0][3] += q0*k3;
            acc[1][0] += q1*k0; acc[1][1] += q1*k1; acc[1][2] += q1*k2; acc[1][3] += q1*k3;
            acc[2][0] += q2*k0; acc[2][1] += q2*k1; acc[2][2] += q2*k2; acc[2][3] += q2*k3;
            acc[3][0] += q3*k0; acc[3][1] += q3*k1; acc[3][2] += q3*k2; acc[3][3] += q3*k3;
        }
    }
    #pragma unroll
    for (int i = 0; i < 4; i++)
        #pragma unroll
        for (int l = 0; l < 4; l++)
            atomicAdd(&g_S[(size_t)bh*576 + (c0+i)*24 + (d0+l)], acc[i][l]);
}

// ---------------- softmax + M = Wproj @ blockdiag(attn) ----------------
__global__ __launch_bounds__(192) void k_soft(const float* __restrict__ temp,
                                              const float* __restrict__ resc,
                                              const float* __restrict__ wproj)
{
    __shared__ float a[24][24];
    const int h = blockIdx.x, b = blockIdx.y;
    const int tid = threadIdx.x;
    const float* Sp = g_S + (size_t)(b*8 + h) * 576;
    const float t = temp[h];
    for (int idx = tid; idx < 576; idx += 192) {
        int c = idx / 24, d = idx % 24;
        float nq = sqrtf(g_norm[b*384 + h*24 + c]);
        float nk = sqrtf(g_norm[b*384 + 192 + h*24 + d]);
        float denom = fmaxf(nq, 1e-12f) * fmaxf(nk, 1e-12f);
        float l = Sp[idx] / denom * t;
        if (c == d) l += resc[h] * g_var[b*192 + h*24 + c];
        a[c][d] = l;
    }
    __syncthreads();
    if (tid < 24) {
        const int c = tid;
        float m = -1e30f;
        #pragma unroll
        for (int d = 0; d < 24; d++) m = fmaxf(m, a[c][d]);
        float e[24]; float ssum = 0.f;
        #pragma unroll
        for (int d = 0; d < 24; d++) { e[d] = expf(a[c][d] - m); ssum += e[d]; }
        float inv = 1.f / ssum;
        #pragma unroll
        for (int d = 0; d < 24; d++) a[c][d] = e[d] * inv;
    }
    __syncthreads();
    const int co = tid;
    float wr[24];
    #pragma unroll
    for (int c = 0; c < 24; c++) wr[c] = wproj[(size_t)co*CDIM + h*24 + c];
    float* Mp = g_M + (size_t)b*CDIM*CDIM + (size_t)co*CDIM + h*24;
    #pragma unroll 4
    for (int d = 0; d < 24; d++) {
        float accv = 0.f;
        #pragma unroll
        for (int c = 0; c < 24; c++) accv += wr[c] * a[c][d];
        Mp[d] = accv;
    }
}

// ---------------- launch ----------------
extern "C" void kernel_launch(void* const* d_in, const int* in_sizes, int n_in,
                              void* d_out, int out_size)
{
    const float* x       = (const float*)d_in[0];
    const float* w_dw    = (const float*)d_in[1];
    const float* w_qkv   = (const float*)d_in[2];
    const float* w_qkvdw = (const float*)d_in[3];
    const float* w_proj  = (const float*)d_in[4];
    const float* temp    = (const float*)d_in[5];
    const float* resc    = (const float*)d_in[6];
    float* out = (float*)d_out;

    float *vprep, *vp, *Mp;
    __nv_bfloat16 *qkbp, *xbp, *wqkbp;
    cudaGetSymbolAddress((void**)&qkbp,  g_qkb);
    cudaGetSymbolAddress((void**)&xbp,   g_xb);
    cudaGetSymbolAddress((void**)&wqkbp, g_wqkb);
    cudaGetSymbolAddress((void**)&vprep, g_vpre);
    cudaGetSymbolAddress((void**)&vp,    g_v);
    cudaGetSymbolAddress((void**)&Mp,    g_M);

    cudaFuncSetAttribute(gemm_mma,  cudaFuncAttributePreferredSharedMemoryCarveout, 90);
    cudaFuncSetAttribute(gemm_bf16, cudaFuncAttributePreferredSharedMemoryCarveout, 90);

    k_zero<<<72, 1024>>>(w_qkv);
    k_dw_var<<<BATCH*CDIM, 256>>>(x, w_dw);     // also emits g_xb (bf16 x)
    // q,k rows of 1x1 conv (bf16 tensor path): [384,HW] = Wqk[384,192] @ xb[192,HW]
    gemm_bf16<<<dim3(6, 64, BATCH), 256>>>(wqkbp, xbp, qkbp);
    // v rows (fp32/tf32 path): [192,HW] = Wv[192,192] @ x[192,HW]
    gemm_mma<<<dim3(3, 64, BATCH), 256>>>(w_qkv + (size_t)384*CDIM, x, vprep,
        CDIM, HW, CDIM, 0LL, (long long)CDIM*HW, (long long)CDIM*HW);
    k_dw_qkv<<<BATCH*C3, 256>>>(w_qkvdw);
    k_qk<<<dim3(64, 16), 144>>>();
    k_soft<<<dim3(HEADS, BATCH), 192>>>(temp, resc, w_proj);
    // final: out[b] = M[b](192x192) @ V[b](192,HW)
    gemm_mma<<<dim3(3, 64, BATCH), 256>>>(Mp, vp, out,
        CDIM, HW, CDIM, (long long)CDIM*CDIM, (long long)CDIM*HW, (long long)CDIM*HW);
}